// round 5
// baseline (speedup 1.0000x reference)
#include <cuda_runtime.h>
#include <cuda_bf16.h>
#include <float.h>

// ---------------------------------------------------------------------------
// DGCNN forward, restructured:
//   EdgeConv(X, W, g, b):  P = X W_a^T ; Q = X (W_b - W_a)^T
//   out[n,c] = bn_lrelu( max_j P[knn(n,j), c] + Q[n,c] )
// kNN via threshold-first filtering:
//   thr[row] = 20th-NN distance to a 256-point subset (valid upper bound)
//   full dist GEMM never materializes: epilogue pushes only dist<=thr survivors
//   exact top-20 selected from ~320 candidates per row (u64 keys -> determinism)
// ---------------------------------------------------------------------------

#define BATCH 8
#define NPTS  4096
#define KNN   20
#define NROWS (BATCH * NPTS)   // 32768
#define EPS_BN 1e-5f
#define SLOPE 0.2f
#define NSUB  256              // subset size for threshold
#define CAND_CAP 2048          // per-row candidate capacity (E~320, 24 sigma)

// ----------------------------- scratch (device globals) --------------------
__device__ float g_x0[NROWS * 3];
__device__ float g_h[(size_t)NROWS * 512];
__device__ float g_sq[NROWS];
__device__ int   g_idx[NROWS * KNN];
__device__ float g_PQ[(size_t)NROWS * 512];
__device__ float g_wcomb[512 * 128];
__device__ float g_y[(size_t)NROWS * 512];        // final acts; also subset-dist scratch
__device__ float g_thr[NROWS];
__device__ int   g_cnt[NROWS];
__device__ unsigned long long g_cand[(size_t)NROWS * CAND_CAP];  // 512MB
__device__ float g_pmax[BATCH * 32 * 512];
__device__ float g_psum[BATCH * 32 * 512];

// ----------------------------- helpers ---------------------------------------

__device__ __forceinline__ unsigned int float_key(float f) {
    unsigned int b = __float_as_uint(f);
    unsigned int mask = (unsigned int)(((int)b) >> 31) | 0x80000000u;
    return b ^ mask;   // monotone: smaller float -> smaller uint
}
__device__ __forceinline__ float key_to_float(unsigned int k) {
    unsigned int b = (k & 0x80000000u) ? (k ^ 0x80000000u) : ~k;
    return __uint_as_float(b);
}
__device__ __forceinline__ void chain_insert20(unsigned long long loc[KNN],
                                               unsigned long long v) {
#pragma unroll
    for (int t = 0; t < KNN; ++t) {
        if (v < loc[t]) { unsigned long long tmp = loc[t]; loc[t] = v; v = tmp; }
    }
}

// ----------------------------- small kernels --------------------------------

__global__ void transpose_x_kernel(const float* __restrict__ x, float* __restrict__ xt) {
    int i = blockIdx.x * blockDim.x + threadIdx.x;
    const int total = BATCH * 3 * NPTS;
    if (i >= total) return;
    int b = i / (3 * NPTS);
    int rem = i % (3 * NPTS);
    int d = rem / NPTS;
    int n = rem % NPTS;
    xt[((size_t)b * NPTS + n) * 3 + d] = x[i];
}

__global__ void sqnorm_kernel(const float* __restrict__ X, int lda, int D,
                              float* __restrict__ sq) {
    int i = blockIdx.x * blockDim.x + threadIdx.x;
    if (i >= NROWS) return;
    const float* r = X + (size_t)i * lda;
    float s = 0.f;
    for (int d = 0; d < D; ++d) s += r[d] * r[d];
    sq[i] = s;
}

__global__ void zero_cnt_kernel(int* __restrict__ cnt) {
    int i = blockIdx.x * blockDim.x + threadIdx.x;
    if (i < NROWS) cnt[i] = 0;
}

// Wc rows 0..C-1 = W_a ; rows C..2C-1 = W_b - W_a
__global__ void wcomb_kernel(const float* __restrict__ W, float* __restrict__ Wc,
                             int C, int D) {
    int i = blockIdx.x * blockDim.x + threadIdx.x;
    if (i >= 2 * C * D) return;
    int c = i / D, d = i % D;
    Wc[i] = (c < C) ? W[c * 2 * D + d]
                    : (W[(c - C) * 2 * D + D + d] - W[(c - C) * 2 * D + d]);
}

// ----------------------------- GEMM ------------------------------------------
// NT GEMM:  C[m,n] = sum_k A[m,k] * B[n,k]
// mode 0: plain store ; mode 1: dist epilogue store ; mode 2: bn+lrelu store
// mode 3: dist + threshold filter -> push survivors to per-row candidate buffer
#define TBM 128
#define TBN 128
#define TBK 8

__global__ __launch_bounds__(256, 2)
void gemm_nt_kernel(const float* __restrict__ A, int lda, long long sA,
                    const float* __restrict__ Bw, int ldb, long long sB,
                    float* __restrict__ C, int ldc, long long sC,
                    int M, int Nn, int K, int mode,
                    const float* __restrict__ sq, long long sSq,
                    const float* __restrict__ gamma, const float* __restrict__ beta,
                    const float* __restrict__ thr, int* __restrict__ cnt,
                    unsigned long long* __restrict__ cand) {
    int bz = blockIdx.z;
    A  += (long long)bz * sA;
    Bw += (long long)bz * sB;
    if (C) C += (long long)bz * sC;
    const float* sqp = sq ? (sq + (long long)bz * sSq) : nullptr;
    const float* thrp = thr ? (thr + (long long)bz * NPTS) : nullptr;
    int* cntp = cnt ? (cnt + (long long)bz * NPTS) : nullptr;
    unsigned long long* candp = cand ? (cand + (size_t)bz * NPTS * CAND_CAP) : nullptr;

    __shared__ float As[TBK][TBM + 4];
    __shared__ float Bs[TBK][TBN + 4];

    const int m0 = blockIdx.y * TBM;
    const int n0 = blockIdx.x * TBN;
    const int tid = threadIdx.x;
    const int tn = tid % 16;
    const int tm = tid / 16;

    float acc[8][8];
#pragma unroll
    for (int i = 0; i < 8; ++i)
#pragma unroll
        for (int j = 0; j < 8; ++j) acc[i][j] = 0.f;

    const bool vec = ((lda % 4) == 0) && ((ldb % 4) == 0) && ((K % TBK) == 0);
    const int lr = tid >> 1;
    const int lp = (tid & 1) * 4;

    for (int k0 = 0; k0 < K; k0 += TBK) {
        if (vec) {
            float4 va = *(const float4*)(A + (long long)(m0 + lr) * lda + k0 + lp);
            float4 vb = *(const float4*)(Bw + (long long)(n0 + lr) * ldb + k0 + lp);
            As[lp + 0][lr] = va.x; As[lp + 1][lr] = va.y;
            As[lp + 2][lr] = va.z; As[lp + 3][lr] = va.w;
            Bs[lp + 0][lr] = vb.x; Bs[lp + 1][lr] = vb.y;
            Bs[lp + 2][lr] = vb.z; Bs[lp + 3][lr] = vb.w;
        } else {
            for (int i = tid; i < TBM * TBK; i += 256) {
                int mm = i % TBM, kk = i / TBM;
                int gk = k0 + kk;
                As[kk][mm] = (gk < K) ? A[(long long)(m0 + mm) * lda + gk] : 0.f;
            }
            for (int i = tid; i < TBN * TBK; i += 256) {
                int nn = i % TBN, kk = i / TBN;
                int gk = k0 + kk;
                Bs[kk][nn] = (gk < K) ? Bw[(long long)(n0 + nn) * ldb + gk] : 0.f;
            }
        }
        __syncthreads();
#pragma unroll
        for (int kk = 0; kk < TBK; ++kk) {
            float ra[8], rb[8];
            const float4* pa = (const float4*)&As[kk][tm * 8];
            const float4* pb = (const float4*)&Bs[kk][tn * 8];
            float4 a0 = pa[0], a1 = pa[1];
            float4 b0 = pb[0], b1 = pb[1];
            ra[0] = a0.x; ra[1] = a0.y; ra[2] = a0.z; ra[3] = a0.w;
            ra[4] = a1.x; ra[5] = a1.y; ra[6] = a1.z; ra[7] = a1.w;
            rb[0] = b0.x; rb[1] = b0.y; rb[2] = b0.z; rb[3] = b0.w;
            rb[4] = b1.x; rb[5] = b1.y; rb[6] = b1.z; rb[7] = b1.w;
#pragma unroll
            for (int i = 0; i < 8; ++i)
#pragma unroll
                for (int j = 0; j < 8; ++j) acc[i][j] += ra[i] * rb[j];
        }
        __syncthreads();
    }

    if (mode == 3) {
        // dist + filter: no store of the dist matrix
#pragma unroll
        for (int i = 0; i < 8; ++i) {
            int gm = m0 + tm * 8 + i;
            float sm = sqp[gm];
            float tr = thrp[gm];
#pragma unroll
            for (int j = 0; j < 8; ++j) {
                int gn = n0 + tn * 8 + j;
                float v = sm + sqp[gn] - 2.f * acc[i][j];
                if (v <= tr) {
                    int pos = atomicAdd(&cntp[gm], 1);
                    if (pos < CAND_CAP)
                        candp[(size_t)gm * CAND_CAP + pos] =
                            ((unsigned long long)float_key(v) << 32) | (unsigned int)gn;
                }
            }
        }
        return;
    }

#pragma unroll
    for (int i = 0; i < 8; ++i) {
        int gm = m0 + tm * 8 + i;
        float* crow = C + (long long)gm * ldc + n0 + tn * 8;
        float v[8];
        if (mode == 1) {
            float sm = sqp[gm];
#pragma unroll
            for (int j = 0; j < 8; ++j) {
                int gn = n0 + tn * 8 + j;
                v[j] = sm + sqp[gn] - 2.f * acc[i][j];
            }
        } else if (mode == 2) {
#pragma unroll
            for (int j = 0; j < 8; ++j) {
                int gn = n0 + tn * 8 + j;
                float s = gamma[gn] * rsqrtf(1.0f + EPS_BN);
                float t = acc[i][j] * s + beta[gn];
                v[j] = (t >= 0.f) ? t : SLOPE * t;
            }
        } else {
#pragma unroll
            for (int j = 0; j < 8; ++j) v[j] = acc[i][j];
        }
        ((float4*)crow)[0] = make_float4(v[0], v[1], v[2], v[3]);
        ((float4*)crow)[1] = make_float4(v[4], v[5], v[6], v[7]);
    }
}

// ----------------------------- threshold from subset -------------------------
// One warp per row over NSUB=256 subset distances -> thr = 20th smallest.
__global__ __launch_bounds__(256)
void thr_kernel(const float* __restrict__ sd, float* __restrict__ thr) {
    int warp = (blockIdx.x * blockDim.x + threadIdx.x) >> 5;
    int lane = threadIdx.x & 31;
    if (warp >= NROWS) return;
    const float4* row4 = (const float4*)(sd + (size_t)warp * NSUB);

    const unsigned long long SENT = 0xFFFFFFFFFFFFFFFFULL;
    unsigned long long loc[KNN];
#pragma unroll
    for (int t = 0; t < KNN; ++t) loc[t] = SENT;

#pragma unroll
    for (int g = 0; g < 2; ++g) {
        float4 v = row4[g * 32 + lane];
        unsigned int j = (g * 32 + lane) * 4;
        chain_insert20(loc, ((unsigned long long)float_key(v.x) << 32) | (j + 0));
        chain_insert20(loc, ((unsigned long long)float_key(v.y) << 32) | (j + 1));
        chain_insert20(loc, ((unsigned long long)float_key(v.z) << 32) | (j + 2));
        chain_insert20(loc, ((unsigned long long)float_key(v.w) << 32) | (j + 3));
    }

    float thr_f = 0.f;
#pragma unroll
    for (int s = 0; s < KNN; ++s) {
        unsigned long long v = loc[0];
        int wl = lane;
#pragma unroll
        for (int off = 16; off > 0; off >>= 1) {
            unsigned long long ov = __shfl_down_sync(0xFFFFFFFFu, v, off);
            int owl = __shfl_down_sync(0xFFFFFFFFu, wl, off);
            if (ov < v) { v = ov; wl = owl; }
        }
        unsigned long long win = __shfl_sync(0xFFFFFFFFu, v, 0);
        int wlane = __shfl_sync(0xFFFFFFFFu, wl, 0);
        if (lane == wlane) {
#pragma unroll
            for (int t = 0; t < KNN - 1; ++t) loc[t] = loc[t + 1];
            loc[KNN - 1] = SENT;
        }
        thr_f = key_to_float((unsigned int)(win >> 32));
    }
    if (lane == 0) thr[warp] = thr_f;
}

// ----------------------------- exact top-20 from candidates ------------------
// One warp per row. Per-lane chain of 20 guarantees no loss for any count.
__global__ __launch_bounds__(256)
void cand_topk_kernel(const unsigned long long* __restrict__ cand,
                      const int* __restrict__ cnt, int* __restrict__ out) {
    int warp = (blockIdx.x * blockDim.x + threadIdx.x) >> 5;
    int lane = threadIdx.x & 31;
    if (warp >= NROWS) return;
    int c = cnt[warp];
    if (c > CAND_CAP) c = CAND_CAP;
    const unsigned long long* buf = cand + (size_t)warp * CAND_CAP;

    const unsigned long long SENT = 0xFFFFFFFFFFFFFFFFULL;
    unsigned long long loc[KNN];
#pragma unroll
    for (int t = 0; t < KNN; ++t) loc[t] = SENT;
    for (int i = lane; i < c; i += 32) chain_insert20(loc, buf[i]);

#pragma unroll
    for (int s = 0; s < KNN; ++s) {
        unsigned long long v = loc[0];
        int wl = lane;
#pragma unroll
        for (int off = 16; off > 0; off >>= 1) {
            unsigned long long ov = __shfl_down_sync(0xFFFFFFFFu, v, off);
            int owl = __shfl_down_sync(0xFFFFFFFFu, wl, off);
            if (ov < v) { v = ov; wl = owl; }
        }
        unsigned long long win = __shfl_sync(0xFFFFFFFFu, v, 0);
        int wlane = __shfl_sync(0xFFFFFFFFu, wl, 0);
        if (lane == 0) out[(size_t)warp * KNN + s] = (int)(win & 0xFFFFFFFFu);
        if (lane == wlane) {
#pragma unroll
            for (int t = 0; t < KNN - 1; ++t) loc[t] = loc[t + 1];
            loc[KNN - 1] = SENT;
        }
    }
}

// ----------------------------- gather + epilogue -----------------------------
__global__ void gather_max_bn_kernel(const float* __restrict__ PQ,
                                     const int* __restrict__ idx,
                                     const float* __restrict__ gamma,
                                     const float* __restrict__ beta,
                                     float* __restrict__ out, int outLd, int C) {
    __shared__ int sidx[KNN];
    int point = blockIdx.x;
    int b = point / NPTS;
    if (threadIdx.x < KNN) sidx[threadIdx.x] = idx[(size_t)point * KNN + threadIdx.x];
    __syncthreads();
    int c = threadIdx.x;
    int ld = 2 * C;
    float m = -FLT_MAX;
#pragma unroll 4
    for (int j = 0; j < KNN; ++j) {
        size_t row = (size_t)b * NPTS + sidx[j];
        m = fmaxf(m, PQ[row * ld + c]);
    }
    float v = m + PQ[(size_t)point * ld + C + c];
    float s = gamma[c] * rsqrtf(1.0f + EPS_BN);
    v = v * s + beta[c];
    v = (v >= 0.f) ? v : SLOPE * v;
    out[(size_t)point * outLd + c] = v;
}

// ----------------------------- two-stage pool --------------------------------
#define PCHUNK 32
#define PSTEP (NPTS / PCHUNK)

__global__ void reduce1_kernel(const float* __restrict__ y,
                               float* __restrict__ pmax, float* __restrict__ psum) {
    int b = blockIdx.y;
    int q = blockIdx.x;
    int c = threadIdx.x;
    const float* p = y + ((size_t)b * NPTS + (size_t)q * PSTEP) * 512 + c;
    float mx = -FLT_MAX, sm = 0.f;
#pragma unroll 4
    for (int n = 0; n < PSTEP; ++n) {
        float v = p[(size_t)n * 512];
        mx = fmaxf(mx, v);
        sm += v;
    }
    pmax[(b * PCHUNK + q) * 512 + c] = mx;
    psum[(b * PCHUNK + q) * 512 + c] = sm;
}

__global__ void reduce2_kernel(const float* __restrict__ pmax,
                               const float* __restrict__ psum,
                               float* __restrict__ out) {
    int b = blockIdx.x;
    int c = threadIdx.x;
    float mx = -FLT_MAX, sm = 0.f;
#pragma unroll
    for (int q = 0; q < PCHUNK; ++q) {
        mx = fmaxf(mx, pmax[(b * PCHUNK + q) * 512 + c]);
        sm += psum[(b * PCHUNK + q) * 512 + c];
    }
    out[b * 1024 + c]       = mx;
    out[b * 1024 + 512 + c] = sm * (1.0f / NPTS);
}

// ----------------------------- host driver ----------------------------------

static void run_edge_conv(const float* X, int lda, int D, int C,
                          const float* W, const float* g, const float* b,
                          float* h_out_col,
                          float* p_sq, float* p_sub, float* p_thr, int* p_cnt,
                          unsigned long long* p_cand, int* p_idx,
                          float* p_PQ, float* p_wc) {
    sqnorm_kernel<<<(NROWS + 255) / 256, 256>>>(X, lda, D, p_sq);

    // subset dist: every point vs first NSUB points of its batch
    dim3 gs(NSUB / TBN, NPTS / TBM, BATCH);
    gemm_nt_kernel<<<gs, 256>>>(X, lda, (long long)NPTS * lda,
                                X, lda, (long long)NPTS * lda,
                                p_sub, NSUB, (long long)NPTS * NSUB,
                                NPTS, NSUB, D, 1,
                                p_sq, NPTS, nullptr, nullptr,
                                nullptr, nullptr, nullptr);

    thr_kernel<<<NROWS / 8, 256>>>(p_sub, p_thr);
    zero_cnt_kernel<<<NROWS / 256, 256>>>(p_cnt);

    // full dist with threshold filter (no dist store)
    dim3 gd(NPTS / TBN, NPTS / TBM, BATCH);
    gemm_nt_kernel<<<gd, 256>>>(X, lda, (long long)NPTS * lda,
                                X, lda, (long long)NPTS * lda,
                                nullptr, 0, 0,
                                NPTS, NPTS, D, 3,
                                p_sq, NPTS, nullptr, nullptr,
                                p_thr, p_cnt, p_cand);

    cand_topk_kernel<<<NROWS / 8, 256>>>(p_cand, p_cnt, p_idx);

    wcomb_kernel<<<(2 * C * D + 255) / 256, 256>>>(W, p_wc, C, D);

    dim3 gp((2 * C) / TBN, NROWS / TBM, 1);
    gemm_nt_kernel<<<gp, 256>>>(X, lda, 0, p_wc, D, 0,
                                p_PQ, 2 * C, 0, NROWS, 2 * C, D, 0,
                                nullptr, 0, nullptr, nullptr,
                                nullptr, nullptr, nullptr);

    gather_max_bn_kernel<<<NROWS, C>>>(p_PQ, p_idx, g, b, h_out_col, 512, C);
}

extern "C" void kernel_launch(void* const* d_in, const int* in_sizes, int n_in,
                              void* d_out, int out_size) {
    const float* x = (const float*)d_in[0];
    int wb = 1;
    if (n_in > 1 && in_sizes[1] == 1) wb = 2;

    const float* W1 = (const float*)d_in[wb + 0];
    const float* g1 = (const float*)d_in[wb + 1];
    const float* b1 = (const float*)d_in[wb + 2];
    const float* W2 = (const float*)d_in[wb + 3];
    const float* g2 = (const float*)d_in[wb + 4];
    const float* b2 = (const float*)d_in[wb + 5];
    const float* W3 = (const float*)d_in[wb + 6];
    const float* g3 = (const float*)d_in[wb + 7];
    const float* b3 = (const float*)d_in[wb + 8];
    const float* W4 = (const float*)d_in[wb + 9];
    const float* g4 = (const float*)d_in[wb + 10];
    const float* b4 = (const float*)d_in[wb + 11];
    const float* W5 = (const float*)d_in[wb + 12];
    const float* g5 = (const float*)d_in[wb + 13];
    const float* b5 = (const float*)d_in[wb + 14];

    void *p;
    cudaGetSymbolAddress(&p, g_x0);    float* x0   = (float*)p;
    cudaGetSymbolAddress(&p, g_h);     float* h    = (float*)p;
    cudaGetSymbolAddress(&p, g_sq);    float* sq   = (float*)p;
    cudaGetSymbolAddress(&p, g_idx);   int*   idx  = (int*)p;
    cudaGetSymbolAddress(&p, g_PQ);    float* PQ   = (float*)p;
    cudaGetSymbolAddress(&p, g_wcomb); float* wc   = (float*)p;
    cudaGetSymbolAddress(&p, g_y);     float* y    = (float*)p;
    cudaGetSymbolAddress(&p, g_thr);   float* thr  = (float*)p;
    cudaGetSymbolAddress(&p, g_cnt);   int*   cnt  = (int*)p;
    cudaGetSymbolAddress(&p, g_cand);  unsigned long long* cand = (unsigned long long*)p;
    cudaGetSymbolAddress(&p, g_pmax);  float* pmax = (float*)p;
    cudaGetSymbolAddress(&p, g_psum);  float* psum = (float*)p;

    transpose_x_kernel<<<(BATCH * 3 * NPTS + 255) / 256, 256>>>(x, x0);

    // g_y doubles as subset-dist scratch (only needed as activations at the end)
    run_edge_conv(x0,      3,   3,   64,  W1, g1, b1, h + 0,   sq, y, thr, cnt, cand, idx, PQ, wc);
    run_edge_conv(h + 0,   512, 64,  64,  W2, g2, b2, h + 64,  sq, y, thr, cnt, cand, idx, PQ, wc);
    run_edge_conv(h + 64,  512, 64,  128, W3, g3, b3, h + 128, sq, y, thr, cnt, cand, idx, PQ, wc);
    run_edge_conv(h + 128, 512, 128, 256, W4, g4, b4, h + 256, sq, y, thr, cnt, cand, idx, PQ, wc);

    dim3 gf(512 / TBN, NROWS / TBM, 1);
    gemm_nt_kernel<<<gf, 256>>>(h, 512, 0, W5, 512, 0,
                                y, 512, 0, NROWS, 512, 512, 2,
                                nullptr, 0, g5, b5,
                                nullptr, nullptr, nullptr);

    reduce1_kernel<<<dim3(PCHUNK, BATCH), 512>>>(y, pmax, psum);
    reduce2_kernel<<<BATCH, 512>>>(pmax, psum, (float*)d_out);
}

// round 6
// speedup vs baseline: 1.4535x; 1.4535x over previous
#include <cuda_runtime.h>
#include <cuda_bf16.h>
#include <float.h>

// ---------------------------------------------------------------------------
// DGCNN forward, restructured:
//   EdgeConv(X, W, g, b):  P = X W_a^T ; Q = X (W_b - W_a)^T
//   out[n,c] = bn_lrelu( max_j P[knn(n,j), c] + Q[n,c] )
// kNN via threshold-first filtering (dist matrix never materialized):
//   thr[row] = 20th smallest dist to a 256-point subset (valid upper bound)
//   filter GEMM pushes dist<=thr survivors (E~335/row) via half-warp
//   aggregated atomics; exact top-20 from candidates (u64 keys, deterministic)
// ---------------------------------------------------------------------------

#define BATCH 8
#define NPTS  4096
#define KNN   20
#define NROWS (BATCH * NPTS)   // 32768
#define EPS_BN 1e-5f
#define SLOPE 0.2f
#define NSUB  256
#define CAND_CAP 2048
#define CNT_STRIDE 8           // 32B padding between counters

// ----------------------------- scratch (device globals) --------------------
__device__ float g_x0[NROWS * 3];
__device__ float g_h[(size_t)NROWS * 512];
__device__ float g_sq[NROWS];
__device__ int   g_idx[NROWS * KNN];
__device__ float g_PQ[(size_t)NROWS * 512];
__device__ float g_wcomb[512 * 128];
__device__ float g_y[(size_t)NROWS * 512];        // final acts; also subset-dist scratch
__device__ float g_thr[NROWS];
__device__ int   g_cnt[NROWS * CNT_STRIDE];
__device__ unsigned long long g_cand[(size_t)NROWS * CAND_CAP];
__device__ float g_pmax[BATCH * 32 * 512];
__device__ float g_psum[BATCH * 32 * 512];

// ----------------------------- helpers ---------------------------------------

__device__ __forceinline__ unsigned int float_key(float f) {
    unsigned int b = __float_as_uint(f);
    unsigned int mask = (unsigned int)(((int)b) >> 31) | 0x80000000u;
    return b ^ mask;   // monotone: smaller float -> smaller uint
}
__device__ __forceinline__ float key_to_float(unsigned int k) {
    unsigned int b = (k & 0x80000000u) ? (k ^ 0x80000000u) : ~k;
    return __uint_as_float(b);
}
__device__ __forceinline__ void chain_insert20(unsigned long long loc[KNN],
                                               unsigned long long v) {
#pragma unroll
    for (int t = 0; t < KNN; ++t) {
        if (v < loc[t]) { unsigned long long tmp = loc[t]; loc[t] = v; v = tmp; }
    }
}

// ----------------------------- small kernels --------------------------------

__global__ void transpose_x_kernel(const float* __restrict__ x, float* __restrict__ xt) {
    int i = blockIdx.x * blockDim.x + threadIdx.x;
    const int total = BATCH * 3 * NPTS;
    if (i >= total) return;
    int b = i / (3 * NPTS);
    int rem = i % (3 * NPTS);
    int d = rem / NPTS;
    int n = rem % NPTS;
    xt[((size_t)b * NPTS + n) * 3 + d] = x[i];
}

__global__ void sqnorm_kernel(const float* __restrict__ X, int lda, int D,
                              float* __restrict__ sq) {
    int i = blockIdx.x * blockDim.x + threadIdx.x;
    if (i >= NROWS) return;
    const float* r = X + (size_t)i * lda;
    float s = 0.f;
    for (int d = 0; d < D; ++d) s += r[d] * r[d];
    sq[i] = s;
}

__global__ void zero_cnt_kernel(int* __restrict__ cnt) {
    int i = blockIdx.x * blockDim.x + threadIdx.x;
    if (i < NROWS * CNT_STRIDE) cnt[i] = 0;
}

// Wc rows 0..C-1 = W_a ; rows C..2C-1 = W_b - W_a
__global__ void wcomb_kernel(const float* __restrict__ W, float* __restrict__ Wc,
                             int C, int D) {
    int i = blockIdx.x * blockDim.x + threadIdx.x;
    if (i >= 2 * C * D) return;
    int c = i / D, d = i % D;
    Wc[i] = (c < C) ? W[c * 2 * D + d]
                    : (W[(c - C) * 2 * D + D + d] - W[(c - C) * 2 * D + d]);
}

// ----------------------------- GEMM ------------------------------------------
// NT GEMM:  C[m,n] = sum_k A[m,k] * B[n,k]
// MODE 0: plain store ; MODE 1: dist store ; MODE 2: bn+lrelu store
// MODE 3: dist + threshold filter -> candidate push (no C store)
#define TBM 128
#define TBN 128
#define TBK 8

template <int MODE>
__global__ __launch_bounds__(256, 2)
void gemm_nt_kernel(const float* __restrict__ A, int lda, long long sA,
                    const float* __restrict__ Bw, int ldb, long long sB,
                    float* __restrict__ C, int ldc, long long sC,
                    int M, int Nn, int K,
                    const float* __restrict__ sq, long long sSq,
                    const float* __restrict__ gamma, const float* __restrict__ beta,
                    const float* __restrict__ thr, int* __restrict__ cnt,
                    unsigned long long* __restrict__ cand) {
    int bz = blockIdx.z;
    A  += (long long)bz * sA;
    Bw += (long long)bz * sB;
    if (MODE != 3) C += (long long)bz * sC;
    const float* sqp = (MODE == 1 || MODE == 3) ? (sq + (long long)bz * sSq) : nullptr;
    const float* thrp = (MODE == 3) ? (thr + (long long)bz * NPTS) : nullptr;
    int* cntp = (MODE == 3) ? (cnt + (long long)bz * NPTS * CNT_STRIDE) : nullptr;
    unsigned long long* candp = (MODE == 3) ? (cand + (size_t)bz * NPTS * CAND_CAP) : nullptr;

    __shared__ float As[TBK][TBM + 4];
    __shared__ float Bs[TBK][TBN + 4];

    const int m0 = blockIdx.y * TBM;
    const int n0 = blockIdx.x * TBN;
    const int tid = threadIdx.x;
    const int tn = tid % 16;
    const int tm = tid / 16;

    float acc[8][8];
#pragma unroll
    for (int i = 0; i < 8; ++i)
#pragma unroll
        for (int j = 0; j < 8; ++j) acc[i][j] = 0.f;

    const bool vec = ((lda % 4) == 0) && ((ldb % 4) == 0) && ((K % TBK) == 0);
    const int lr = tid >> 1;
    const int lp = (tid & 1) * 4;

    for (int k0 = 0; k0 < K; k0 += TBK) {
        if (vec) {
            float4 va = *(const float4*)(A + (long long)(m0 + lr) * lda + k0 + lp);
            float4 vb = *(const float4*)(Bw + (long long)(n0 + lr) * ldb + k0 + lp);
            As[lp + 0][lr] = va.x; As[lp + 1][lr] = va.y;
            As[lp + 2][lr] = va.z; As[lp + 3][lr] = va.w;
            Bs[lp + 0][lr] = vb.x; Bs[lp + 1][lr] = vb.y;
            Bs[lp + 2][lr] = vb.z; Bs[lp + 3][lr] = vb.w;
        } else {
            for (int i = tid; i < TBM * TBK; i += 256) {
                int mm = i % TBM, kk = i / TBM;
                int gk = k0 + kk;
                As[kk][mm] = (gk < K) ? A[(long long)(m0 + mm) * lda + gk] : 0.f;
            }
            for (int i = tid; i < TBN * TBK; i += 256) {
                int nn = i % TBN, kk = i / TBN;
                int gk = k0 + kk;
                Bs[kk][nn] = (gk < K) ? Bw[(long long)(n0 + nn) * ldb + gk] : 0.f;
            }
        }
        __syncthreads();
#pragma unroll
        for (int kk = 0; kk < TBK; ++kk) {
            float ra[8], rb[8];
            const float4* pa = (const float4*)&As[kk][tm * 8];
            const float4* pb = (const float4*)&Bs[kk][tn * 8];
            float4 a0 = pa[0], a1 = pa[1];
            float4 b0 = pb[0], b1 = pb[1];
            ra[0] = a0.x; ra[1] = a0.y; ra[2] = a0.z; ra[3] = a0.w;
            ra[4] = a1.x; ra[5] = a1.y; ra[6] = a1.z; ra[7] = a1.w;
            rb[0] = b0.x; rb[1] = b0.y; rb[2] = b0.z; rb[3] = b0.w;
            rb[4] = b1.x; rb[5] = b1.y; rb[6] = b1.z; rb[7] = b1.w;
#pragma unroll
            for (int i = 0; i < 8; ++i)
#pragma unroll
                for (int j = 0; j < 8; ++j) acc[i][j] += ra[i] * rb[j];
        }
        __syncthreads();
    }

    if (MODE == 3) {
        // Half-warp (16 lanes sharing tm) owns each output row of this tile.
        const int lane = tid & 31;
        const int lane16 = lane & 15;                 // == tn
        const unsigned hw_shift = (lane >> 4) * 16;
        const unsigned hwmask = 0xFFFFu << hw_shift;
        const unsigned below = ((1u << lane16) - 1u) << hw_shift;
#pragma unroll
        for (int i = 0; i < 8; ++i) {
            int gm = m0 + tm * 8 + i;
            float sm = sqp[gm];
            float tr = thrp[gm];
            float v[8];
            unsigned pb[8];
            int rank[8];
            int cum = 0;
#pragma unroll
            for (int j = 0; j < 8; ++j) {
                int gn = n0 + tn * 8 + j;
                v[j] = sm + sqp[gn] - 2.f * acc[i][j];
                unsigned ball = __ballot_sync(0xFFFFFFFFu, v[j] <= tr) & hwmask;
                rank[j] = cum + __popc(ball & below);
                cum += __popc(ball);
                pb[j] = ball;
            }
            if (cum > 0) {   // uniform within the half-warp
                int base = 0;
                if (lane16 == 0) base = atomicAdd(&cntp[gm * CNT_STRIDE], cum);
                base = __shfl_sync(hwmask, base, hw_shift);
                unsigned long long* dst = candp + (size_t)gm * CAND_CAP;
#pragma unroll
                for (int j = 0; j < 8; ++j) {
                    if (pb[j] & (1u << lane)) {
                        int pos = base + rank[j];
                        if (pos < CAND_CAP) {
                            int gn = n0 + tn * 8 + j;
                            dst[pos] = ((unsigned long long)float_key(v[j]) << 32)
                                       | (unsigned int)gn;
                        }
                    }
                }
            }
        }
        return;
    }

#pragma unroll
    for (int i = 0; i < 8; ++i) {
        int gm = m0 + tm * 8 + i;
        float* crow = C + (long long)gm * ldc + n0 + tn * 8;
        float v[8];
        if (MODE == 1) {
            float sm = sqp[gm];
#pragma unroll
            for (int j = 0; j < 8; ++j) {
                int gn = n0 + tn * 8 + j;
                v[j] = sm + sqp[gn] - 2.f * acc[i][j];
            }
        } else if (MODE == 2) {
#pragma unroll
            for (int j = 0; j < 8; ++j) {
                int gn = n0 + tn * 8 + j;
                float s = gamma[gn] * rsqrtf(1.0f + EPS_BN);
                float t = acc[i][j] * s + beta[gn];
                v[j] = (t >= 0.f) ? t : SLOPE * t;
            }
        } else {
#pragma unroll
            for (int j = 0; j < 8; ++j) v[j] = acc[i][j];
        }
        ((float4*)crow)[0] = make_float4(v[0], v[1], v[2], v[3]);
        ((float4*)crow)[1] = make_float4(v[4], v[5], v[6], v[7]);
    }
}

// ----------------------------- threshold from subset -------------------------
__global__ __launch_bounds__(256)
void thr_kernel(const float* __restrict__ sd, float* __restrict__ thr) {
    int warp = (blockIdx.x * blockDim.x + threadIdx.x) >> 5;
    int lane = threadIdx.x & 31;
    if (warp >= NROWS) return;
    const float4* row4 = (const float4*)(sd + (size_t)warp * NSUB);

    const unsigned long long SENT = 0xFFFFFFFFFFFFFFFFULL;
    unsigned long long loc[KNN];
#pragma unroll
    for (int t = 0; t < KNN; ++t) loc[t] = SENT;

#pragma unroll
    for (int g = 0; g < 2; ++g) {
        float4 v = row4[g * 32 + lane];
        unsigned int j = (g * 32 + lane) * 4;
        chain_insert20(loc, ((unsigned long long)float_key(v.x) << 32) | (j + 0));
        chain_insert20(loc, ((unsigned long long)float_key(v.y) << 32) | (j + 1));
        chain_insert20(loc, ((unsigned long long)float_key(v.z) << 32) | (j + 2));
        chain_insert20(loc, ((unsigned long long)float_key(v.w) << 32) | (j + 3));
    }

    float thr_f = 0.f;
#pragma unroll
    for (int s = 0; s < KNN; ++s) {
        unsigned long long v = loc[0];
        int wl = lane;
#pragma unroll
        for (int off = 16; off > 0; off >>= 1) {
            unsigned long long ov = __shfl_down_sync(0xFFFFFFFFu, v, off);
            int owl = __shfl_down_sync(0xFFFFFFFFu, wl, off);
            if (ov < v) { v = ov; wl = owl; }
        }
        unsigned long long win = __shfl_sync(0xFFFFFFFFu, v, 0);
        int wlane = __shfl_sync(0xFFFFFFFFu, wl, 0);
        if (lane == wlane) {
#pragma unroll
            for (int t = 0; t < KNN - 1; ++t) loc[t] = loc[t + 1];
            loc[KNN - 1] = SENT;
        }
        thr_f = key_to_float((unsigned int)(win >> 32));
    }
    if (lane == 0) thr[warp] = thr_f;
}

// ----------------------------- exact top-20 from candidates ------------------
__global__ __launch_bounds__(256)
void cand_topk_kernel(const unsigned long long* __restrict__ cand,
                      const int* __restrict__ cnt, int* __restrict__ out) {
    int warp = (blockIdx.x * blockDim.x + threadIdx.x) >> 5;
    int lane = threadIdx.x & 31;
    if (warp >= NROWS) return;
    int c = cnt[warp * CNT_STRIDE];
    if (c > CAND_CAP) c = CAND_CAP;
    const unsigned long long* buf = cand + (size_t)warp * CAND_CAP;

    const unsigned long long SENT = 0xFFFFFFFFFFFFFFFFULL;
    unsigned long long loc[KNN];
#pragma unroll
    for (int t = 0; t < KNN; ++t) loc[t] = SENT;
    for (int i = lane; i < c; i += 32) chain_insert20(loc, buf[i]);

#pragma unroll
    for (int s = 0; s < KNN; ++s) {
        unsigned long long v = loc[0];
        int wl = lane;
#pragma unroll
        for (int off = 16; off > 0; off >>= 1) {
            unsigned long long ov = __shfl_down_sync(0xFFFFFFFFu, v, off);
            int owl = __shfl_down_sync(0xFFFFFFFFu, wl, off);
            if (ov < v) { v = ov; wl = owl; }
        }
        unsigned long long win = __shfl_sync(0xFFFFFFFFu, v, 0);
        int wlane = __shfl_sync(0xFFFFFFFFu, wl, 0);
        if (lane == 0) out[(size_t)warp * KNN + s] = (int)(win & 0xFFFFFFFFu);
        if (lane == wlane) {
#pragma unroll
            for (int t = 0; t < KNN - 1; ++t) loc[t] = loc[t + 1];
            loc[KNN - 1] = SENT;
        }
    }
}

// ----------------------------- gather + epilogue -----------------------------
__global__ void gather_max_bn_kernel(const float* __restrict__ PQ,
                                     const int* __restrict__ idx,
                                     const float* __restrict__ gamma,
                                     const float* __restrict__ beta,
                                     float* __restrict__ out, int outLd, int C) {
    __shared__ int sidx[KNN];
    int point = blockIdx.x;
    int b = point / NPTS;
    if (threadIdx.x < KNN) sidx[threadIdx.x] = idx[(size_t)point * KNN + threadIdx.x];
    __syncthreads();
    int c = threadIdx.x;
    int ld = 2 * C;
    float m = -FLT_MAX;
#pragma unroll 4
    for (int j = 0; j < KNN; ++j) {
        size_t row = (size_t)b * NPTS + sidx[j];
        m = fmaxf(m, PQ[row * ld + c]);
    }
    float v = m + PQ[(size_t)point * ld + C + c];
    float s = gamma[c] * rsqrtf(1.0f + EPS_BN);
    v = v * s + beta[c];
    v = (v >= 0.f) ? v : SLOPE * v;
    out[(size_t)point * outLd + c] = v;
}

// ----------------------------- two-stage pool --------------------------------
#define PCHUNK 32
#define PSTEP (NPTS / PCHUNK)

__global__ void reduce1_kernel(const float* __restrict__ y,
                               float* __restrict__ pmax, float* __restrict__ psum) {
    int b = blockIdx.y;
    int q = blockIdx.x;
    int c = threadIdx.x;
    const float* p = y + ((size_t)b * NPTS + (size_t)q * PSTEP) * 512 + c;
    float mx = -FLT_MAX, sm = 0.f;
#pragma unroll 4
    for (int n = 0; n < PSTEP; ++n) {
        float v = p[(size_t)n * 512];
        mx = fmaxf(mx, v);
        sm += v;
    }
    pmax[(b * PCHUNK + q) * 512 + c] = mx;
    psum[(b * PCHUNK + q) * 512 + c] = sm;
}

__global__ void reduce2_kernel(const float* __restrict__ pmax,
                               const float* __restrict__ psum,
                               float* __restrict__ out) {
    int b = blockIdx.x;
    int c = threadIdx.x;
    float mx = -FLT_MAX, sm = 0.f;
#pragma unroll
    for (int q = 0; q < PCHUNK; ++q) {
        mx = fmaxf(mx, pmax[(b * PCHUNK + q) * 512 + c]);
        sm += psum[(b * PCHUNK + q) * 512 + c];
    }
    out[b * 1024 + c]       = mx;
    out[b * 1024 + 512 + c] = sm * (1.0f / NPTS);
}

// ----------------------------- host driver ----------------------------------

static void run_edge_conv(const float* X, int lda, int D, int C,
                          const float* W, const float* g, const float* b,
                          float* h_out_col,
                          float* p_sq, float* p_sub, float* p_thr, int* p_cnt,
                          unsigned long long* p_cand, int* p_idx,
                          float* p_PQ, float* p_wc) {
    sqnorm_kernel<<<(NROWS + 255) / 256, 256>>>(X, lda, D, p_sq);

    // subset dist: every point vs first NSUB points of its batch
    dim3 gs(NSUB / TBN, NPTS / TBM, BATCH);
    gemm_nt_kernel<1><<<gs, 256>>>(X, lda, (long long)NPTS * lda,
                                   X, lda, (long long)NPTS * lda,
                                   p_sub, NSUB, (long long)NPTS * NSUB,
                                   NPTS, NSUB, D,
                                   p_sq, NPTS, nullptr, nullptr,
                                   nullptr, nullptr, nullptr);

    thr_kernel<<<NROWS / 8, 256>>>(p_sub, p_thr);
    zero_cnt_kernel<<<(NROWS * CNT_STRIDE) / 256, 256>>>(p_cnt);

    // full dist with threshold filter (no dist store)
    dim3 gd(NPTS / TBN, NPTS / TBM, BATCH);
    gemm_nt_kernel<3><<<gd, 256>>>(X, lda, (long long)NPTS * lda,
                                   X, lda, (long long)NPTS * lda,
                                   nullptr, 0, 0,
                                   NPTS, NPTS, D,
                                   p_sq, NPTS, nullptr, nullptr,
                                   p_thr, p_cnt, p_cand);

    cand_topk_kernel<<<NROWS / 8, 256>>>(p_cand, p_cnt, p_idx);

    wcomb_kernel<<<(2 * C * D + 255) / 256, 256>>>(W, p_wc, C, D);

    dim3 gp((2 * C) / TBN, NROWS / TBM, 1);
    gemm_nt_kernel<0><<<gp, 256>>>(X, lda, 0, p_wc, D, 0,
                                   p_PQ, 2 * C, 0, NROWS, 2 * C, D,
                                   nullptr, 0, nullptr, nullptr,
                                   nullptr, nullptr, nullptr);

    gather_max_bn_kernel<<<NROWS, C>>>(p_PQ, p_idx, g, b, h_out_col, 512, C);
}

extern "C" void kernel_launch(void* const* d_in, const int* in_sizes, int n_in,
                              void* d_out, int out_size) {
    const float* x = (const float*)d_in[0];
    int wb = 1;
    if (n_in > 1 && in_sizes[1] == 1) wb = 2;

    const float* W1 = (const float*)d_in[wb + 0];
    const float* g1 = (const float*)d_in[wb + 1];
    const float* b1 = (const float*)d_in[wb + 2];
    const float* W2 = (const float*)d_in[wb + 3];
    const float* g2 = (const float*)d_in[wb + 4];
    const float* b2 = (const float*)d_in[wb + 5];
    const float* W3 = (const float*)d_in[wb + 6];
    const float* g3 = (const float*)d_in[wb + 7];
    const float* b3 = (const float*)d_in[wb + 8];
    const float* W4 = (const float*)d_in[wb + 9];
    const float* g4 = (const float*)d_in[wb + 10];
    const float* b4 = (const float*)d_in[wb + 11];
    const float* W5 = (const float*)d_in[wb + 12];
    const float* g5 = (const float*)d_in[wb + 13];
    const float* b5 = (const float*)d_in[wb + 14];

    void *p;
    cudaGetSymbolAddress(&p, g_x0);    float* x0   = (float*)p;
    cudaGetSymbolAddress(&p, g_h);     float* h    = (float*)p;
    cudaGetSymbolAddress(&p, g_sq);    float* sq   = (float*)p;
    cudaGetSymbolAddress(&p, g_idx);   int*   idx  = (int*)p;
    cudaGetSymbolAddress(&p, g_PQ);    float* PQ   = (float*)p;
    cudaGetSymbolAddress(&p, g_wcomb); float* wc   = (float*)p;
    cudaGetSymbolAddress(&p, g_y);     float* y    = (float*)p;
    cudaGetSymbolAddress(&p, g_thr);   float* thr  = (float*)p;
    cudaGetSymbolAddress(&p, g_cnt);   int*   cnt  = (int*)p;
    cudaGetSymbolAddress(&p, g_cand);  unsigned long long* cand = (unsigned long long*)p;
    cudaGetSymbolAddress(&p, g_pmax);  float* pmax = (float*)p;
    cudaGetSymbolAddress(&p, g_psum);  float* psum = (float*)p;

    transpose_x_kernel<<<(BATCH * 3 * NPTS + 255) / 256, 256>>>(x, x0);

    run_edge_conv(x0,      3,   3,   64,  W1, g1, b1, h + 0,   sq, y, thr, cnt, cand, idx, PQ, wc);
    run_edge_conv(h + 0,   512, 64,  64,  W2, g2, b2, h + 64,  sq, y, thr, cnt, cand, idx, PQ, wc);
    run_edge_conv(h + 64,  512, 64,  128, W3, g3, b3, h + 128, sq, y, thr, cnt, cand, idx, PQ, wc);
    run_edge_conv(h + 128, 512, 128, 256, W4, g4, b4, h + 256, sq, y, thr, cnt, cand, idx, PQ, wc);

    dim3 gf(512 / TBN, NROWS / TBM, 1);
    gemm_nt_kernel<2><<<gf, 256>>>(h, 512, 0, W5, 512, 0,
                                   y, 512, 0, NROWS, 512, 512,
                                   nullptr, 0, g5, b5,
                                   nullptr, nullptr, nullptr);

    reduce1_kernel<<<dim3(PCHUNK, BATCH), 512>>>(y, pmax, psum);
    reduce2_kernel<<<BATCH, 512>>>(pmax, psum, (float*)d_out);
}

// round 7
// speedup vs baseline: 1.6880x; 1.1614x over previous
#include <cuda_runtime.h>
#include <cuda_bf16.h>
#include <float.h>

// ---------------------------------------------------------------------------
// DGCNN forward, restructured:
//   EdgeConv(X, W, g, b):  P = X W_a^T ; Q = X (W_b - W_a)^T
//   out[n,c] = bn_lrelu( max_j P[knn(n,j), c] + Q[n,c] )
// kNN via threshold-first filtering (dist matrix never materialized):
//   thr[row] = 20th smallest dist to a 256-point subset (valid upper bound)
//   SYMMETRIC filter GEMM over the upper block-triangle pushes each surviving
//   pair to both rows via warp-local aggregated atomics.
// ---------------------------------------------------------------------------

#define BATCH 8
#define NPTS  4096
#define KNN   20
#define NROWS (BATCH * NPTS)   // 32768
#define EPS_BN 1e-5f
#define SLOPE 0.2f
#define NSUB  256
#define CAND_CAP 2048
#define CNT_STRIDE 8           // 32B padding between counters
#define NT 32                  // 4096/128 tiles per side
#define NPAIRS (NT * (NT + 1) / 2)   // 528

// ----------------------------- scratch (device globals) --------------------
__device__ float g_x0[NROWS * 3];
__device__ float g_h[(size_t)NROWS * 512];
__device__ float g_sq[NROWS];
__device__ int   g_idx[NROWS * KNN];
__device__ float g_PQ[(size_t)NROWS * 512];
__device__ float g_wcomb[512 * 128];
__device__ float g_y[(size_t)NROWS * 512];        // final acts; also subset-dist scratch
__device__ float g_thr[NROWS];
__device__ int   g_cnt[NROWS * CNT_STRIDE];
__device__ unsigned long long g_cand[(size_t)NROWS * CAND_CAP];
__device__ float g_pmax[BATCH * 32 * 512];
__device__ float g_psum[BATCH * 32 * 512];

// ----------------------------- helpers ---------------------------------------

__device__ __forceinline__ unsigned int float_key(float f) {
    unsigned int b = __float_as_uint(f);
    unsigned int mask = (unsigned int)(((int)b) >> 31) | 0x80000000u;
    return b ^ mask;   // monotone: smaller float -> smaller uint
}
__device__ __forceinline__ float key_to_float(unsigned int k) {
    unsigned int b = (k & 0x80000000u) ? (k ^ 0x80000000u) : ~k;
    return __uint_as_float(b);
}
// Identical FP sequence in subset GEMM and filter kernel (no reassociation).
__device__ __forceinline__ float dist_val(float sm, float sn, float acc) {
    return __fmaf_rn(-2.0f, acc, __fadd_rn(sm, sn));
}
__device__ __forceinline__ void chain_insert20(unsigned long long loc[KNN],
                                               unsigned long long v) {
#pragma unroll
    for (int t = 0; t < KNN; ++t) {
        if (v < loc[t]) { unsigned long long tmp = loc[t]; loc[t] = v; v = tmp; }
    }
}

// ----------------------------- small kernels --------------------------------

__global__ void transpose_x_kernel(const float* __restrict__ x, float* __restrict__ xt) {
    int i = blockIdx.x * blockDim.x + threadIdx.x;
    const int total = BATCH * 3 * NPTS;
    if (i >= total) return;
    int b = i / (3 * NPTS);
    int rem = i % (3 * NPTS);
    int d = rem / NPTS;
    int n = rem % NPTS;
    xt[((size_t)b * NPTS + n) * 3 + d] = x[i];
}

__global__ void sqnorm_kernel(const float* __restrict__ X, int lda, int D,
                              float* __restrict__ sq) {
    int i = blockIdx.x * blockDim.x + threadIdx.x;
    if (i >= NROWS) return;
    const float* r = X + (size_t)i * lda;
    float s = 0.f;
    for (int d = 0; d < D; ++d) s += r[d] * r[d];
    sq[i] = s;
}

__global__ void zero_cnt_kernel(int* __restrict__ cnt) {
    int i = blockIdx.x * blockDim.x + threadIdx.x;
    if (i < NROWS * CNT_STRIDE) cnt[i] = 0;
}

// Wc rows 0..C-1 = W_a ; rows C..2C-1 = W_b - W_a
__global__ void wcomb_kernel(const float* __restrict__ W, float* __restrict__ Wc,
                             int C, int D) {
    int i = blockIdx.x * blockDim.x + threadIdx.x;
    if (i >= 2 * C * D) return;
    int c = i / D, d = i % D;
    Wc[i] = (c < C) ? W[c * 2 * D + d]
                    : (W[(c - C) * 2 * D + D + d] - W[(c - C) * 2 * D + d]);
}

// ----------------------------- GEMM (store modes) ----------------------------
// NT GEMM:  C[m,n] = sum_k A[m,k] * B[n,k]
// MODE 0: plain store ; MODE 1: dist store ; MODE 2: bn+lrelu store
#define TBM 128
#define TBN 128
#define TBK 8

template <int MODE>
__global__ __launch_bounds__(256, 2)
void gemm_nt_kernel(const float* __restrict__ A, int lda, long long sA,
                    const float* __restrict__ Bw, int ldb, long long sB,
                    float* __restrict__ C, int ldc, long long sC,
                    int M, int Nn, int K,
                    const float* __restrict__ sq, long long sSq,
                    const float* __restrict__ gamma, const float* __restrict__ beta) {
    int bz = blockIdx.z;
    A  += (long long)bz * sA;
    Bw += (long long)bz * sB;
    C  += (long long)bz * sC;
    const float* sqp = (MODE == 1) ? (sq + (long long)bz * sSq) : nullptr;

    __shared__ float As[TBK][TBM + 4];
    __shared__ float Bs[TBK][TBN + 4];

    const int m0 = blockIdx.y * TBM;
    const int n0 = blockIdx.x * TBN;
    const int tid = threadIdx.x;
    const int tn = tid % 16;
    const int tm = tid / 16;

    float acc[8][8];
#pragma unroll
    for (int i = 0; i < 8; ++i)
#pragma unroll
        for (int j = 0; j < 8; ++j) acc[i][j] = 0.f;

    const bool vec = ((lda % 4) == 0) && ((ldb % 4) == 0) && ((K % TBK) == 0);
    const int lr = tid >> 1;
    const int lp = (tid & 1) * 4;

    for (int k0 = 0; k0 < K; k0 += TBK) {
        if (vec) {
            float4 va = *(const float4*)(A + (long long)(m0 + lr) * lda + k0 + lp);
            float4 vb = *(const float4*)(Bw + (long long)(n0 + lr) * ldb + k0 + lp);
            As[lp + 0][lr] = va.x; As[lp + 1][lr] = va.y;
            As[lp + 2][lr] = va.z; As[lp + 3][lr] = va.w;
            Bs[lp + 0][lr] = vb.x; Bs[lp + 1][lr] = vb.y;
            Bs[lp + 2][lr] = vb.z; Bs[lp + 3][lr] = vb.w;
        } else {
            for (int i = tid; i < TBM * TBK; i += 256) {
                int mm = i % TBM, kk = i / TBM;
                int gk = k0 + kk;
                As[kk][mm] = (gk < K) ? A[(long long)(m0 + mm) * lda + gk] : 0.f;
            }
            for (int i = tid; i < TBN * TBK; i += 256) {
                int nn = i % TBN, kk = i / TBN;
                int gk = k0 + kk;
                Bs[kk][nn] = (gk < K) ? Bw[(long long)(n0 + nn) * ldb + gk] : 0.f;
            }
        }
        __syncthreads();
#pragma unroll
        for (int kk = 0; kk < TBK; ++kk) {
            float ra[8], rb[8];
            const float4* pa = (const float4*)&As[kk][tm * 8];
            const float4* pb = (const float4*)&Bs[kk][tn * 8];
            float4 a0 = pa[0], a1 = pa[1];
            float4 b0 = pb[0], b1 = pb[1];
            ra[0] = a0.x; ra[1] = a0.y; ra[2] = a0.z; ra[3] = a0.w;
            ra[4] = a1.x; ra[5] = a1.y; ra[6] = a1.z; ra[7] = a1.w;
            rb[0] = b0.x; rb[1] = b0.y; rb[2] = b0.z; rb[3] = b0.w;
            rb[4] = b1.x; rb[5] = b1.y; rb[6] = b1.z; rb[7] = b1.w;
#pragma unroll
            for (int i = 0; i < 8; ++i)
#pragma unroll
                for (int j = 0; j < 8; ++j) acc[i][j] += ra[i] * rb[j];
        }
        __syncthreads();
    }

#pragma unroll
    for (int i = 0; i < 8; ++i) {
        int gm = m0 + tm * 8 + i;
        float* crow = C + (long long)gm * ldc + n0 + tn * 8;
        float v[8];
        if (MODE == 1) {
            float sm = sqp[gm];
#pragma unroll
            for (int j = 0; j < 8; ++j) {
                int gn = n0 + tn * 8 + j;
                v[j] = dist_val(sm, sqp[gn], acc[i][j]);
            }
        } else if (MODE == 2) {
#pragma unroll
            for (int j = 0; j < 8; ++j) {
                int gn = n0 + tn * 8 + j;
                float s = gamma[gn] * rsqrtf(1.0f + EPS_BN);
                float t = acc[i][j] * s + beta[gn];
                v[j] = (t >= 0.f) ? t : SLOPE * t;
            }
        } else {
#pragma unroll
            for (int j = 0; j < 8; ++j) v[j] = acc[i][j];
        }
        ((float4*)crow)[0] = make_float4(v[0], v[1], v[2], v[3]);
        ((float4*)crow)[1] = make_float4(v[4], v[5], v[6], v[7]);
    }
}

// ----------------------- symmetric dist filter (triangular) ------------------
// Upper block-triangle tiles only. Warp owns a 32x64 subtile (4x2 warp grid,
// lane = ly*8+lx, each thread 8x8). Row push: 8-lane groups (ly fixed).
// Col push (off-diagonal tiles only): 4-lane strided groups (lx fixed).
__global__ __launch_bounds__(256, 2)
void dist_filter_kernel(const float* __restrict__ X, int lda, int K,
                        const float* __restrict__ sq,
                        const float* __restrict__ thr,
                        int* __restrict__ cnt,
                        unsigned long long* __restrict__ cand) {
    const int bz = blockIdx.z;
    const float* A = X + (long long)bz * NPTS * lda;
    const float* sqp = sq + (long long)bz * NPTS;
    const float* thrp = thr + (long long)bz * NPTS;
    int* cntp = cnt + (long long)bz * NPTS * CNT_STRIDE;
    unsigned long long* candp = cand + (size_t)bz * NPTS * CAND_CAP;

    // triangular decode: pair index -> (ty, tx), tx >= ty
    int t = blockIdx.x, ty = 0;
    while (t >= NT - ty) { t -= NT - ty; ++ty; }
    const int tx = ty + t;
    const int m0 = ty * TBM;
    const int n0 = tx * TBN;
    const bool offdiag = (tx > ty);

    __shared__ float As[TBK][TBM + 4];
    __shared__ float Bs[TBK][TBN + 4];

    const int tid = threadIdx.x;
    const int warp = tid >> 5;
    const int lane = tid & 31;
    const int wy = warp >> 1;            // 0..3
    const int wx = warp & 1;             // 0..1
    const int ly = lane >> 3;            // 0..3
    const int lx = lane & 7;             // 0..7
    const int row_off = wy * 32 + ly * 8;
    const int col_off = wx * 64 + lx * 8;

    float acc[8][8];
#pragma unroll
    for (int i = 0; i < 8; ++i)
#pragma unroll
        for (int j = 0; j < 8; ++j) acc[i][j] = 0.f;

    const bool vec = ((lda % 4) == 0) && ((K % TBK) == 0);
    const int lr = tid >> 1;
    const int lp = (tid & 1) * 4;

    for (int k0 = 0; k0 < K; k0 += TBK) {
        if (vec) {
            float4 va = *(const float4*)(A + (long long)(m0 + lr) * lda + k0 + lp);
            float4 vb = *(const float4*)(A + (long long)(n0 + lr) * lda + k0 + lp);
            As[lp + 0][lr] = va.x; As[lp + 1][lr] = va.y;
            As[lp + 2][lr] = va.z; As[lp + 3][lr] = va.w;
            Bs[lp + 0][lr] = vb.x; Bs[lp + 1][lr] = vb.y;
            Bs[lp + 2][lr] = vb.z; Bs[lp + 3][lr] = vb.w;
        } else {
            for (int i = tid; i < TBM * TBK; i += 256) {
                int mm = i % TBM, kk = i / TBM;
                int gk = k0 + kk;
                As[kk][mm] = (gk < K) ? A[(long long)(m0 + mm) * lda + gk] : 0.f;
            }
            for (int i = tid; i < TBN * TBK; i += 256) {
                int nn = i % TBN, kk = i / TBN;
                int gk = k0 + kk;
                Bs[kk][nn] = (gk < K) ? A[(long long)(n0 + nn) * lda + gk] : 0.f;
            }
        }
        __syncthreads();
#pragma unroll
        for (int kk = 0; kk < TBK; ++kk) {
            float ra[8], rb[8];
            const float4* pa = (const float4*)&As[kk][row_off];
            const float4* pb = (const float4*)&Bs[kk][col_off];
            float4 a0 = pa[0], a1 = pa[1];
            float4 b0 = pb[0], b1 = pb[1];
            ra[0] = a0.x; ra[1] = a0.y; ra[2] = a0.z; ra[3] = a0.w;
            ra[4] = a1.x; ra[5] = a1.y; ra[6] = a1.z; ra[7] = a1.w;
            rb[0] = b0.x; rb[1] = b0.y; rb[2] = b0.z; rb[3] = b0.w;
            rb[4] = b1.x; rb[5] = b1.y; rb[6] = b1.z; rb[7] = b1.w;
#pragma unroll
            for (int i = 0; i < 8; ++i)
#pragma unroll
                for (int j = 0; j < 8; ++j) acc[i][j] += ra[i] * rb[j];
        }
        __syncthreads();
    }

    // v[i][j] in-place
    float sm[8], sn[8], trr[8], trc[8];
#pragma unroll
    for (int i = 0; i < 8; ++i) {
        sm[i] = sqp[m0 + row_off + i];
        trr[i] = thrp[m0 + row_off + i];
    }
#pragma unroll
    for (int j = 0; j < 8; ++j) {
        sn[j] = sqp[n0 + col_off + j];
        trc[j] = thrp[n0 + col_off + j];
    }
#pragma unroll
    for (int i = 0; i < 8; ++i)
#pragma unroll
        for (int j = 0; j < 8; ++j)
            acc[i][j] = dist_val(sm[i], sn[j], acc[i][j]);

    // ---- row push: 8-lane groups (ly fixed), leader lane = ly*8 ----
    {
        const unsigned grp = 0xFFu << (ly * 8);
        const unsigned below = ((1u << lx) - 1u) << (ly * 8);
        const int leader_lane = ly * 8;
#pragma unroll
        for (int i = 0; i < 8; ++i) {
            const int gm = m0 + row_off + i;
            unsigned pb[8];
            int rank[8];
            int cum = 0;
#pragma unroll
            for (int j = 0; j < 8; ++j) {
                unsigned ball = __ballot_sync(0xFFFFFFFFu, acc[i][j] <= trr[i]) & grp;
                rank[j] = cum + __popc(ball & below);
                cum += __popc(ball);
                pb[j] = ball;
            }
            int base = 0;
            if (lx == 0 && cum > 0) base = atomicAdd(&cntp[gm * CNT_STRIDE], cum);
            base = __shfl_sync(0xFFFFFFFFu, base, leader_lane);
            if (cum > 0) {
                unsigned long long* dst = candp + (size_t)gm * CAND_CAP;
#pragma unroll
                for (int j = 0; j < 8; ++j) {
                    if (pb[j] & (1u << lane)) {
                        int pos = base + rank[j];
                        if (pos < CAND_CAP) {
                            int gn = n0 + col_off + j;
                            dst[pos] = ((unsigned long long)float_key(acc[i][j]) << 32)
                                       | (unsigned int)gn;
                        }
                    }
                }
            }
        }
    }

    // ---- col push (off-diagonal only): 4-lane strided groups (lx fixed) ----
    if (offdiag) {
        const unsigned grp = 0x01010101u << lx;
        const unsigned below = grp & ((1u << lane) - 1u);
        const int leader_lane = lx;        // ly==0 member
#pragma unroll
        for (int j = 0; j < 8; ++j) {
            const int gn = n0 + col_off + j;
            unsigned pb[8];
            int rank[8];
            int cum = 0;
#pragma unroll
            for (int i = 0; i < 8; ++i) {
                unsigned ball = __ballot_sync(0xFFFFFFFFu, acc[i][j] <= trc[j]) & grp;
                rank[i] = cum + __popc(ball & below);
                cum += __popc(ball);
                pb[i] = ball;
            }
            int base = 0;
            if (ly == 0 && cum > 0) base = atomicAdd(&cntp[gn * CNT_STRIDE], cum);
            base = __shfl_sync(0xFFFFFFFFu, base, leader_lane);
            if (cum > 0) {
                unsigned long long* dst = candp + (size_t)gn * CAND_CAP;
#pragma unroll
                for (int i = 0; i < 8; ++i) {
                    if (pb[i] & (1u << lane)) {
                        int pos = base + rank[i];
                        if (pos < CAND_CAP) {
                            int gm = m0 + row_off + i;
                            dst[pos] = ((unsigned long long)float_key(acc[i][j]) << 32)
                                       | (unsigned int)gm;
                        }
                    }
                }
            }
        }
    }
}

// ----------------------------- threshold from subset -------------------------
__global__ __launch_bounds__(256)
void thr_kernel(const float* __restrict__ sd, float* __restrict__ thr) {
    int warp = (blockIdx.x * blockDim.x + threadIdx.x) >> 5;
    int lane = threadIdx.x & 31;
    if (warp >= NROWS) return;
    const float4* row4 = (const float4*)(sd + (size_t)warp * NSUB);

    const unsigned long long SENT = 0xFFFFFFFFFFFFFFFFULL;
    unsigned long long loc[KNN];
#pragma unroll
    for (int t = 0; t < KNN; ++t) loc[t] = SENT;

#pragma unroll
    for (int g = 0; g < 2; ++g) {
        float4 v = row4[g * 32 + lane];
        unsigned int j = (g * 32 + lane) * 4;
        chain_insert20(loc, ((unsigned long long)float_key(v.x) << 32) | (j + 0));
        chain_insert20(loc, ((unsigned long long)float_key(v.y) << 32) | (j + 1));
        chain_insert20(loc, ((unsigned long long)float_key(v.z) << 32) | (j + 2));
        chain_insert20(loc, ((unsigned long long)float_key(v.w) << 32) | (j + 3));
    }

    float thr_f = 0.f;
#pragma unroll
    for (int s = 0; s < KNN; ++s) {
        unsigned long long v = loc[0];
        int wl = lane;
#pragma unroll
        for (int off = 16; off > 0; off >>= 1) {
            unsigned long long ov = __shfl_down_sync(0xFFFFFFFFu, v, off);
            int owl = __shfl_down_sync(0xFFFFFFFFu, wl, off);
            if (ov < v) { v = ov; wl = owl; }
        }
        unsigned long long win = __shfl_sync(0xFFFFFFFFu, v, 0);
        int wlane = __shfl_sync(0xFFFFFFFFu, wl, 0);
        if (lane == wlane) {
#pragma unroll
            for (int t = 0; t < KNN - 1; ++t) loc[t] = loc[t + 1];
            loc[KNN - 1] = SENT;
        }
        thr_f = key_to_float((unsigned int)(win >> 32));
    }
    if (lane == 0) thr[warp] = thr_f;
}

// ----------------------------- exact top-20 from candidates ------------------
__global__ __launch_bounds__(256)
void cand_topk_kernel(const unsigned long long* __restrict__ cand,
                      const int* __restrict__ cnt, int* __restrict__ out) {
    int warp = (blockIdx.x * blockDim.x + threadIdx.x) >> 5;
    int lane = threadIdx.x & 31;
    if (warp >= NROWS) return;
    int c = cnt[warp * CNT_STRIDE];
    if (c > CAND_CAP) c = CAND_CAP;
    const unsigned long long* buf = cand + (size_t)warp * CAND_CAP;

    const unsigned long long SENT = 0xFFFFFFFFFFFFFFFFULL;
    unsigned long long loc[KNN];
#pragma unroll
    for (int t = 0; t < KNN; ++t) loc[t] = SENT;
    for (int i = lane; i < c; i += 32) chain_insert20(loc, buf[i]);

#pragma unroll
    for (int s = 0; s < KNN; ++s) {
        unsigned long long v = loc[0];
        int wl = lane;
#pragma unroll
        for (int off = 16; off > 0; off >>= 1) {
            unsigned long long ov = __shfl_down_sync(0xFFFFFFFFu, v, off);
            int owl = __shfl_down_sync(0xFFFFFFFFu, wl, off);
            if (ov < v) { v = ov; wl = owl; }
        }
        unsigned long long win = __shfl_sync(0xFFFFFFFFu, v, 0);
        int wlane = __shfl_sync(0xFFFFFFFFu, wl, 0);
        if (lane == 0) out[(size_t)warp * KNN + s] = (int)(win & 0xFFFFFFFFu);
        if (lane == wlane) {
#pragma unroll
            for (int t = 0; t < KNN - 1; ++t) loc[t] = loc[t + 1];
            loc[KNN - 1] = SENT;
        }
    }
}

// ----------------------------- gather + epilogue -----------------------------
__global__ void gather_max_bn_kernel(const float* __restrict__ PQ,
                                     const int* __restrict__ idx,
                                     const float* __restrict__ gamma,
                                     const float* __restrict__ beta,
                                     float* __restrict__ out, int outLd, int C) {
    __shared__ int sidx[KNN];
    int point = blockIdx.x;
    int b = point / NPTS;
    if (threadIdx.x < KNN) sidx[threadIdx.x] = idx[(size_t)point * KNN + threadIdx.x];
    __syncthreads();
    int c = threadIdx.x;
    int ld = 2 * C;
    float m = -FLT_MAX;
#pragma unroll 4
    for (int j = 0; j < KNN; ++j) {
        size_t row = (size_t)b * NPTS + sidx[j];
        m = fmaxf(m, PQ[row * ld + c]);
    }
    float v = m + PQ[(size_t)point * ld + C + c];
    float s = gamma[c] * rsqrtf(1.0f + EPS_BN);
    v = v * s + beta[c];
    v = (v >= 0.f) ? v : SLOPE * v;
    out[(size_t)point * outLd + c] = v;
}

// ----------------------------- two-stage pool --------------------------------
#define PCHUNK 32
#define PSTEP (NPTS / PCHUNK)

__global__ void reduce1_kernel(const float* __restrict__ y,
                               float* __restrict__ pmax, float* __restrict__ psum) {
    int b = blockIdx.y;
    int q = blockIdx.x;
    int c = threadIdx.x;
    const float* p = y + ((size_t)b * NPTS + (size_t)q * PSTEP) * 512 + c;
    float mx = -FLT_MAX, sm = 0.f;
#pragma unroll 4
    for (int n = 0; n < PSTEP; ++n) {
        float v = p[(size_t)n * 512];
        mx = fmaxf(mx, v);
        sm += v;
    }
    pmax[(b * PCHUNK + q) * 512 + c] = mx;
    psum[(b * PCHUNK + q) * 512 + c] = sm;
}

__global__ void reduce2_kernel(const float* __restrict__ pmax,
                               const float* __restrict__ psum,
                               float* __restrict__ out) {
    int b = blockIdx.x;
    int c = threadIdx.x;
    float mx = -FLT_MAX, sm = 0.f;
#pragma unroll
    for (int q = 0; q < PCHUNK; ++q) {
        mx = fmaxf(mx, pmax[(b * PCHUNK + q) * 512 + c]);
        sm += psum[(b * PCHUNK + q) * 512 + c];
    }
    out[b * 1024 + c]       = mx;
    out[b * 1024 + 512 + c] = sm * (1.0f / NPTS);
}

// ----------------------------- host driver ----------------------------------

static void run_edge_conv(const float* X, int lda, int D, int C,
                          const float* W, const float* g, const float* b,
                          float* h_out_col,
                          float* p_sq, float* p_sub, float* p_thr, int* p_cnt,
                          unsigned long long* p_cand, int* p_idx,
                          float* p_PQ, float* p_wc) {
    sqnorm_kernel<<<(NROWS + 255) / 256, 256>>>(X, lda, D, p_sq);

    // subset dist: every point vs first NSUB points of its batch
    dim3 gs(NSUB / TBN, NPTS / TBM, BATCH);
    gemm_nt_kernel<1><<<gs, 256>>>(X, lda, (long long)NPTS * lda,
                                   X, lda, (long long)NPTS * lda,
                                   p_sub, NSUB, (long long)NPTS * NSUB,
                                   NPTS, NSUB, D,
                                   p_sq, NPTS, nullptr, nullptr);

    thr_kernel<<<NROWS / 8, 256>>>(p_sub, p_thr);
    zero_cnt_kernel<<<(NROWS * CNT_STRIDE) / 256, 256>>>(p_cnt);

    // symmetric triangular filter (no dist store)
    dim3 gd(NPAIRS, 1, BATCH);
    dist_filter_kernel<<<gd, 256>>>(X, lda, D, p_sq, p_thr, p_cnt, p_cand);

    cand_topk_kernel<<<NROWS / 8, 256>>>(p_cand, p_cnt, p_idx);

    wcomb_kernel<<<(2 * C * D + 255) / 256, 256>>>(W, p_wc, C, D);

    dim3 gp((2 * C) / TBN, NROWS / TBM, 1);
    gemm_nt_kernel<0><<<gp, 256>>>(X, lda, 0, p_wc, D, 0,
                                   p_PQ, 2 * C, 0, NROWS, 2 * C, D,
                                   nullptr, 0, nullptr, nullptr);

    gather_max_bn_kernel<<<NROWS, C>>>(p_PQ, p_idx, g, b, h_out_col, 512, C);
}

extern "C" void kernel_launch(void* const* d_in, const int* in_sizes, int n_in,
                              void* d_out, int out_size) {
    const float* x = (const float*)d_in[0];
    int wb = 1;
    if (n_in > 1 && in_sizes[1] == 1) wb = 2;

    const float* W1 = (const float*)d_in[wb + 0];
    const float* g1 = (const float*)d_in[wb + 1];
    const float* b1 = (const float*)d_in[wb + 2];
    const float* W2 = (const float*)d_in[wb + 3];
    const float* g2 = (const float*)d_in[wb + 4];
    const float* b2 = (const float*)d_in[wb + 5];
    const float* W3 = (const float*)d_in[wb + 6];
    const float* g3 = (const float*)d_in[wb + 7];
    const float* b3 = (const float*)d_in[wb + 8];
    const float* W4 = (const float*)d_in[wb + 9];
    const float* g4 = (const float*)d_in[wb + 10];
    const float* b4 = (const float*)d_in[wb + 11];
    const float* W5 = (const float*)d_in[wb + 12];
    const float* g5 = (const float*)d_in[wb + 13];
    const float* b5 = (const float*)d_in[wb + 14];

    void *p;
    cudaGetSymbolAddress(&p, g_x0);    float* x0   = (float*)p;
    cudaGetSymbolAddress(&p, g_h);     float* h    = (float*)p;
    cudaGetSymbolAddress(&p, g_sq);    float* sq   = (float*)p;
    cudaGetSymbolAddress(&p, g_idx);   int*   idx  = (int*)p;
    cudaGetSymbolAddress(&p, g_PQ);    float* PQ   = (float*)p;
    cudaGetSymbolAddress(&p, g_wcomb); float* wc   = (float*)p;
    cudaGetSymbolAddress(&p, g_y);     float* y    = (float*)p;
    cudaGetSymbolAddress(&p, g_thr);   float* thr  = (float*)p;
    cudaGetSymbolAddress(&p, g_cnt);   int*   cnt  = (int*)p;
    cudaGetSymbolAddress(&p, g_cand);  unsigned long long* cand = (unsigned long long*)p;
    cudaGetSymbolAddress(&p, g_pmax);  float* pmax = (float*)p;
    cudaGetSymbolAddress(&p, g_psum);  float* psum = (float*)p;

    transpose_x_kernel<<<(BATCH * 3 * NPTS + 255) / 256, 256>>>(x, x0);

    run_edge_conv(x0,      3,   3,   64,  W1, g1, b1, h + 0,   sq, y, thr, cnt, cand, idx, PQ, wc);
    run_edge_conv(h + 0,   512, 64,  64,  W2, g2, b2, h + 64,  sq, y, thr, cnt, cand, idx, PQ, wc);
    run_edge_conv(h + 64,  512, 64,  128, W3, g3, b3, h + 128, sq, y, thr, cnt, cand, idx, PQ, wc);
    run_edge_conv(h + 128, 512, 128, 256, W4, g4, b4, h + 256, sq, y, thr, cnt, cand, idx, PQ, wc);

    dim3 gf(512 / TBN, NROWS / TBM, 1);
    gemm_nt_kernel<2><<<gf, 256>>>(h, 512, 0, W5, 512, 0,
                                   y, 512, 0, NROWS, 512, 512,
                                   nullptr, 0, g5, b5);

    reduce1_kernel<<<dim3(PCHUNK, BATCH), 512>>>(y, pmax, psum);
    reduce2_kernel<<<BATCH, 512>>>(pmax, psum, (float*)d_out);
}

// round 8
// speedup vs baseline: 1.7938x; 1.0626x over previous
#include <cuda_runtime.h>
#include <cuda_bf16.h>
#include <float.h>

// ---------------------------------------------------------------------------
// DGCNN forward, restructured:
//   EdgeConv(X, W, g, b):  P = X W_a^T ; Q = X (W_b - W_a)^T
//   out[n,c] = bn_lrelu( max_j P[knn(n,j), c] + Q[n,c] )
// kNN via threshold-first filtering (dist matrix never materialized):
//   thr[row] = 20th smallest dist to a 256-point subset (valid upper bound)
//   SYMMETRIC filter GEMM over the upper block-triangle pushes each surviving
//   pair to both rows via warp-local aggregated atomics.
// ---------------------------------------------------------------------------

#define BATCH 8
#define NPTS  4096
#define KNN   20
#define NROWS (BATCH * NPTS)   // 32768
#define EPS_BN 1e-5f
#define SLOPE 0.2f
#define NSUB  256
#define CAND_CAP 2048
#define CNT_STRIDE 8           // 32B padding between counters
#define NT 32                  // 4096/128 tiles per side
#define NPAIRS (NT * (NT + 1) / 2)   // 528

// ----------------------------- scratch (device globals) --------------------
__device__ float g_x0[NROWS * 3];
__device__ float g_h[(size_t)NROWS * 512];
__device__ float g_sq[NROWS];
__device__ int   g_idx[NROWS * KNN];
__device__ float g_PQ[(size_t)NROWS * 512];
__device__ float g_wcomb[512 * 128];
__device__ float g_y[(size_t)NROWS * 512];        // final acts; also subset-dist scratch
__device__ float g_thr[NROWS];
__device__ int   g_cnt[NROWS * CNT_STRIDE];
__device__ unsigned long long g_cand[(size_t)NROWS * CAND_CAP];
__device__ float g_pmax[BATCH * 32 * 512];
__device__ float g_psum[BATCH * 32 * 512];

// ----------------------------- helpers ---------------------------------------

__device__ __forceinline__ unsigned int float_key(float f) {
    unsigned int b = __float_as_uint(f);
    unsigned int mask = (unsigned int)(((int)b) >> 31) | 0x80000000u;
    return b ^ mask;   // monotone: smaller float -> smaller uint
}
__device__ __forceinline__ float key_to_float(unsigned int k) {
    unsigned int b = (k & 0x80000000u) ? (k ^ 0x80000000u) : ~k;
    return __uint_as_float(b);
}
// Identical FP sequence in subset GEMM and filter kernel (no reassociation).
__device__ __forceinline__ float dist_val(float sm, float sn, float acc) {
    return __fmaf_rn(-2.0f, acc, __fadd_rn(sm, sn));
}
__device__ __forceinline__ void chain_insert20(unsigned long long loc[KNN],
                                               unsigned long long v) {
#pragma unroll
    for (int t = 0; t < KNN; ++t) {
        if (v < loc[t]) { unsigned long long tmp = loc[t]; loc[t] = v; v = tmp; }
    }
}

// ----------------------------- small kernels --------------------------------

__global__ void transpose_x_kernel(const float* __restrict__ x, float* __restrict__ xt) {
    int i = blockIdx.x * blockDim.x + threadIdx.x;
    const int total = BATCH * 3 * NPTS;
    if (i >= total) return;
    int b = i / (3 * NPTS);
    int rem = i % (3 * NPTS);
    int d = rem / NPTS;
    int n = rem % NPTS;
    xt[((size_t)b * NPTS + n) * 3 + d] = x[i];
}

__global__ void sqnorm_kernel(const float* __restrict__ X, int lda, int D,
                              float* __restrict__ sq) {
    int i = blockIdx.x * blockDim.x + threadIdx.x;
    if (i >= NROWS) return;
    const float* r = X + (size_t)i * lda;
    float s = 0.f;
    for (int d = 0; d < D; ++d) s += r[d] * r[d];
    sq[i] = s;
}

// Wc rows 0..C-1 = W_a ; rows C..2C-1 = W_b - W_a
__global__ void wcomb_kernel(const float* __restrict__ W, float* __restrict__ Wc,
                             int C, int D) {
    int i = blockIdx.x * blockDim.x + threadIdx.x;
    if (i >= 2 * C * D) return;
    int c = i / D, d = i % D;
    Wc[i] = (c < C) ? W[c * 2 * D + d]
                    : (W[(c - C) * 2 * D + D + d] - W[(c - C) * 2 * D + d]);
}

// ----------------------------- GEMM (store modes) ----------------------------
// NT GEMM:  C[m,n] = sum_k A[m,k] * B[n,k]
// MODE 0: plain store ; MODE 1: dist store ; MODE 2: bn+lrelu store
#define TBM 128
#define TBN 128
#define TBK 8

template <int MODE>
__global__ __launch_bounds__(256, 2)
void gemm_nt_kernel(const float* __restrict__ A, int lda, long long sA,
                    const float* __restrict__ Bw, int ldb, long long sB,
                    float* __restrict__ C, int ldc, long long sC,
                    int M, int Nn, int K,
                    const float* __restrict__ sq, long long sSq,
                    const float* __restrict__ gamma, const float* __restrict__ beta) {
    int bz = blockIdx.z;
    A  += (long long)bz * sA;
    Bw += (long long)bz * sB;
    C  += (long long)bz * sC;
    const float* sqp = (MODE == 1) ? (sq + (long long)bz * sSq) : nullptr;

    __shared__ float As[2][TBK][TBM + 4];
    __shared__ float Bs[2][TBK][TBN + 4];

    const int m0 = blockIdx.y * TBM;
    const int n0 = blockIdx.x * TBN;
    const int tid = threadIdx.x;
    const int tn = tid % 16;
    const int tm = tid / 16;

    float acc[8][8];
#pragma unroll
    for (int i = 0; i < 8; ++i)
#pragma unroll
        for (int j = 0; j < 8; ++j) acc[i][j] = 0.f;

    const bool vec = ((lda % 4) == 0) && ((ldb % 4) == 0) && ((K % TBK) == 0);
    const int lr = tid >> 1;
    const int lp = (tid & 1) * 4;

    if (vec) {
        // prologue: tile 0 into buffer 0
        {
            float4 va = *(const float4*)(A + (long long)(m0 + lr) * lda + lp);
            float4 vb = *(const float4*)(Bw + (long long)(n0 + lr) * ldb + lp);
            As[0][lp + 0][lr] = va.x; As[0][lp + 1][lr] = va.y;
            As[0][lp + 2][lr] = va.z; As[0][lp + 3][lr] = va.w;
            Bs[0][lp + 0][lr] = vb.x; Bs[0][lp + 1][lr] = vb.y;
            Bs[0][lp + 2][lr] = vb.z; Bs[0][lp + 3][lr] = vb.w;
        }
        __syncthreads();
        int cur = 0;
        for (int k0 = 0; k0 < K; k0 += TBK) {
            const bool has_next = (k0 + TBK) < K;
            float4 na, nb;
            if (has_next) {
                na = *(const float4*)(A + (long long)(m0 + lr) * lda + k0 + TBK + lp);
                nb = *(const float4*)(Bw + (long long)(n0 + lr) * ldb + k0 + TBK + lp);
            }
#pragma unroll
            for (int kk = 0; kk < TBK; ++kk) {
                float ra[8], rb[8];
                const float4* pa = (const float4*)&As[cur][kk][tm * 8];
                const float4* pb = (const float4*)&Bs[cur][kk][tn * 8];
                float4 a0 = pa[0], a1 = pa[1];
                float4 b0 = pb[0], b1 = pb[1];
                ra[0] = a0.x; ra[1] = a0.y; ra[2] = a0.z; ra[3] = a0.w;
                ra[4] = a1.x; ra[5] = a1.y; ra[6] = a1.z; ra[7] = a1.w;
                rb[0] = b0.x; rb[1] = b0.y; rb[2] = b0.z; rb[3] = b0.w;
                rb[4] = b1.x; rb[5] = b1.y; rb[6] = b1.z; rb[7] = b1.w;
#pragma unroll
                for (int i = 0; i < 8; ++i)
#pragma unroll
                    for (int j = 0; j < 8; ++j) acc[i][j] += ra[i] * rb[j];
            }
            if (has_next) {
                int nxt = cur ^ 1;
                As[nxt][lp + 0][lr] = na.x; As[nxt][lp + 1][lr] = na.y;
                As[nxt][lp + 2][lr] = na.z; As[nxt][lp + 3][lr] = na.w;
                Bs[nxt][lp + 0][lr] = nb.x; Bs[nxt][lp + 1][lr] = nb.y;
                Bs[nxt][lp + 2][lr] = nb.z; Bs[nxt][lp + 3][lr] = nb.w;
            }
            __syncthreads();
            cur ^= 1;
        }
    } else {
        for (int k0 = 0; k0 < K; k0 += TBK) {
            for (int i = tid; i < TBM * TBK; i += 256) {
                int mm = i % TBM, kk = i / TBM;
                int gk = k0 + kk;
                As[0][kk][mm] = (gk < K) ? A[(long long)(m0 + mm) * lda + gk] : 0.f;
            }
            for (int i = tid; i < TBN * TBK; i += 256) {
                int nn = i % TBN, kk = i / TBN;
                int gk = k0 + kk;
                Bs[0][kk][nn] = (gk < K) ? Bw[(long long)(n0 + nn) * ldb + gk] : 0.f;
            }
            __syncthreads();
#pragma unroll
            for (int kk = 0; kk < TBK; ++kk) {
                float ra[8], rb[8];
                const float4* pa = (const float4*)&As[0][kk][tm * 8];
                const float4* pb = (const float4*)&Bs[0][kk][tn * 8];
                float4 a0 = pa[0], a1 = pa[1];
                float4 b0 = pb[0], b1 = pb[1];
                ra[0] = a0.x; ra[1] = a0.y; ra[2] = a0.z; ra[3] = a0.w;
                ra[4] = a1.x; ra[5] = a1.y; ra[6] = a1.z; ra[7] = a1.w;
                rb[0] = b0.x; rb[1] = b0.y; rb[2] = b0.z; rb[3] = b0.w;
                rb[4] = b1.x; rb[5] = b1.y; rb[6] = b1.z; rb[7] = b1.w;
#pragma unroll
                for (int i = 0; i < 8; ++i)
#pragma unroll
                    for (int j = 0; j < 8; ++j) acc[i][j] += ra[i] * rb[j];
            }
            __syncthreads();
        }
    }

#pragma unroll
    for (int i = 0; i < 8; ++i) {
        int gm = m0 + tm * 8 + i;
        float* crow = C + (long long)gm * ldc + n0 + tn * 8;
        float v[8];
        if (MODE == 1) {
            float sm = sqp[gm];
#pragma unroll
            for (int j = 0; j < 8; ++j) {
                int gn = n0 + tn * 8 + j;
                v[j] = dist_val(sm, sqp[gn], acc[i][j]);
            }
        } else if (MODE == 2) {
#pragma unroll
            for (int j = 0; j < 8; ++j) {
                int gn = n0 + tn * 8 + j;
                float s = gamma[gn] * rsqrtf(1.0f + EPS_BN);
                float t = acc[i][j] * s + beta[gn];
                v[j] = (t >= 0.f) ? t : SLOPE * t;
            }
        } else {
#pragma unroll
            for (int j = 0; j < 8; ++j) v[j] = acc[i][j];
        }
        ((float4*)crow)[0] = make_float4(v[0], v[1], v[2], v[3]);
        ((float4*)crow)[1] = make_float4(v[4], v[5], v[6], v[7]);
    }
}

// ----------------------- symmetric dist filter (triangular) ------------------
// Upper block-triangle tiles only. Warp owns a 32x64 subtile (4x2 warp grid,
// lane = ly*8+lx, each thread 8x8). Row push: 8-lane groups (ly fixed).
// Col push (off-diagonal tiles only): 4-lane strided groups (lx fixed).
__global__ __launch_bounds__(256, 2)
void dist_filter_kernel(const float* __restrict__ X, int lda, int K,
                        const float* __restrict__ sq,
                        const float* __restrict__ thr,
                        int* __restrict__ cnt,
                        unsigned long long* __restrict__ cand) {
    const int bz = blockIdx.z;
    const float* A = X + (long long)bz * NPTS * lda;
    const float* sqp = sq + (long long)bz * NPTS;
    const float* thrp = thr + (long long)bz * NPTS;
    int* cntp = cnt + (long long)bz * NPTS * CNT_STRIDE;
    unsigned long long* candp = cand + (size_t)bz * NPTS * CAND_CAP;

    // triangular decode: pair index -> (ty, tx), tx >= ty
    int t = blockIdx.x, ty = 0;
    while (t >= NT - ty) { t -= NT - ty; ++ty; }
    const int tx = ty + t;
    const int m0 = ty * TBM;
    const int n0 = tx * TBN;
    const bool offdiag = (tx > ty);

    __shared__ float As[2][TBK][TBM + 4];
    __shared__ float Bs[2][TBK][TBN + 4];

    const int tid = threadIdx.x;
    const int lane = tid & 31;
    const int warp = tid >> 5;
    const int wy = warp >> 1;            // 0..3
    const int wx = warp & 1;             // 0..1
    const int ly = lane >> 3;            // 0..3
    const int lx = lane & 7;             // 0..7
    const int row_off = wy * 32 + ly * 8;
    const int col_off = wx * 64 + lx * 8;

    float acc[8][8];
#pragma unroll
    for (int i = 0; i < 8; ++i)
#pragma unroll
        for (int j = 0; j < 8; ++j) acc[i][j] = 0.f;

    const bool vec = ((lda % 4) == 0) && ((K % TBK) == 0);
    const int lr = tid >> 1;
    const int lp = (tid & 1) * 4;

    if (vec) {
        {
            float4 va = *(const float4*)(A + (long long)(m0 + lr) * lda + lp);
            float4 vb = *(const float4*)(A + (long long)(n0 + lr) * lda + lp);
            As[0][lp + 0][lr] = va.x; As[0][lp + 1][lr] = va.y;
            As[0][lp + 2][lr] = va.z; As[0][lp + 3][lr] = va.w;
            Bs[0][lp + 0][lr] = vb.x; Bs[0][lp + 1][lr] = vb.y;
            Bs[0][lp + 2][lr] = vb.z; Bs[0][lp + 3][lr] = vb.w;
        }
        __syncthreads();
        int cur = 0;
        for (int k0 = 0; k0 < K; k0 += TBK) {
            const bool has_next = (k0 + TBK) < K;
            float4 na, nb;
            if (has_next) {
                na = *(const float4*)(A + (long long)(m0 + lr) * lda + k0 + TBK + lp);
                nb = *(const float4*)(A + (long long)(n0 + lr) * lda + k0 + TBK + lp);
            }
#pragma unroll
            for (int kk = 0; kk < TBK; ++kk) {
                float ra[8], rb[8];
                const float4* pa = (const float4*)&As[cur][kk][row_off];
                const float4* pb = (const float4*)&Bs[cur][kk][col_off];
                float4 a0 = pa[0], a1 = pa[1];
                float4 b0 = pb[0], b1 = pb[1];
                ra[0] = a0.x; ra[1] = a0.y; ra[2] = a0.z; ra[3] = a0.w;
                ra[4] = a1.x; ra[5] = a1.y; ra[6] = a1.z; ra[7] = a1.w;
                rb[0] = b0.x; rb[1] = b0.y; rb[2] = b0.z; rb[3] = b0.w;
                rb[4] = b1.x; rb[5] = b1.y; rb[6] = b1.z; rb[7] = b1.w;
#pragma unroll
                for (int i = 0; i < 8; ++i)
#pragma unroll
                    for (int j = 0; j < 8; ++j) acc[i][j] += ra[i] * rb[j];
            }
            if (has_next) {
                int nxt = cur ^ 1;
                As[nxt][lp + 0][lr] = na.x; As[nxt][lp + 1][lr] = na.y;
                As[nxt][lp + 2][lr] = na.z; As[nxt][lp + 3][lr] = na.w;
                Bs[nxt][lp + 0][lr] = nb.x; Bs[nxt][lp + 1][lr] = nb.y;
                Bs[nxt][lp + 2][lr] = nb.z; Bs[nxt][lp + 3][lr] = nb.w;
            }
            __syncthreads();
            cur ^= 1;
        }
    } else {
        for (int k0 = 0; k0 < K; k0 += TBK) {
            for (int i = tid; i < TBM * TBK; i += 256) {
                int mm = i % TBM, kk = i / TBM;
                int gk = k0 + kk;
                As[0][kk][mm] = (gk < K) ? A[(long long)(m0 + mm) * lda + gk] : 0.f;
            }
            for (int i = tid; i < TBN * TBK; i += 256) {
                int nn = i % TBN, kk = i / TBN;
                int gk = k0 + kk;
                Bs[0][kk][nn] = (gk < K) ? A[(long long)(n0 + nn) * lda + gk] : 0.f;
            }
            __syncthreads();
#pragma unroll
            for (int kk = 0; kk < TBK; ++kk) {
                float ra[8], rb[8];
                const float4* pa = (const float4*)&As[0][kk][row_off];
                const float4* pb = (const float4*)&Bs[0][kk][col_off];
                float4 a0 = pa[0], a1 = pa[1];
                float4 b0 = pb[0], b1 = pb[1];
                ra[0] = a0.x; ra[1] = a0.y; ra[2] = a0.z; ra[3] = a0.w;
                ra[4] = a1.x; ra[5] = a1.y; ra[6] = a1.z; ra[7] = a1.w;
                rb[0] = b0.x; rb[1] = b0.y; rb[2] = b0.z; rb[3] = b0.w;
                rb[4] = b1.x; rb[5] = b1.y; rb[6] = b1.z; rb[7] = b1.w;
#pragma unroll
                for (int i = 0; i < 8; ++i)
#pragma unroll
                    for (int j = 0; j < 8; ++j) acc[i][j] += ra[i] * rb[j];
            }
            __syncthreads();
        }
    }

    // v[i][j] in-place
    float sm[8], sn[8], trr[8], trc[8];
#pragma unroll
    for (int i = 0; i < 8; ++i) {
        sm[i] = sqp[m0 + row_off + i];
        trr[i] = thrp[m0 + row_off + i];
    }
#pragma unroll
    for (int j = 0; j < 8; ++j) {
        sn[j] = sqp[n0 + col_off + j];
        trc[j] = thrp[n0 + col_off + j];
    }
#pragma unroll
    for (int i = 0; i < 8; ++i)
#pragma unroll
        for (int j = 0; j < 8; ++j)
            acc[i][j] = dist_val(sm[i], sn[j], acc[i][j]);

    // ---- row push: 8-lane groups (ly fixed), leader lane = ly*8 ----
    {
        const unsigned grp = 0xFFu << (ly * 8);
        const unsigned below = ((1u << lx) - 1u) << (ly * 8);
        const int leader_lane = ly * 8;
#pragma unroll
        for (int i = 0; i < 8; ++i) {
            const int gm = m0 + row_off + i;
            unsigned pb[8];
            int rank[8];
            int cum = 0;
#pragma unroll
            for (int j = 0; j < 8; ++j) {
                unsigned ball = __ballot_sync(0xFFFFFFFFu, acc[i][j] <= trr[i]) & grp;
                rank[j] = cum + __popc(ball & below);
                cum += __popc(ball);
                pb[j] = ball;
            }
            int base = 0;
            if (lx == 0 && cum > 0) base = atomicAdd(&cntp[gm * CNT_STRIDE], cum);
            base = __shfl_sync(0xFFFFFFFFu, base, leader_lane);
            if (cum > 0) {
                unsigned long long* dst = candp + (size_t)gm * CAND_CAP;
#pragma unroll
                for (int j = 0; j < 8; ++j) {
                    if (pb[j] & (1u << lane)) {
                        int pos = base + rank[j];
                        if (pos < CAND_CAP) {
                            int gn = n0 + col_off + j;
                            dst[pos] = ((unsigned long long)float_key(acc[i][j]) << 32)
                                       | (unsigned int)gn;
                        }
                    }
                }
            }
        }
    }

    // ---- col push (off-diagonal only): 4-lane strided groups (lx fixed) ----
    if (offdiag) {
        const unsigned grp = 0x01010101u << lx;
        const unsigned below = grp & ((1u << lane) - 1u);
        const int leader_lane = lx;        // ly==0 member
#pragma unroll
        for (int j = 0; j < 8; ++j) {
            const int gn = n0 + col_off + j;
            unsigned pb[8];
            int rank[8];
            int cum = 0;
#pragma unroll
            for (int i = 0; i < 8; ++i) {
                unsigned ball = __ballot_sync(0xFFFFFFFFu, acc[i][j] <= trc[j]) & grp;
                rank[i] = cum + __popc(ball & below);
                cum += __popc(ball);
                pb[i] = ball;
            }
            int base = 0;
            if (ly == 0 && cum > 0) base = atomicAdd(&cntp[gn * CNT_STRIDE], cum);
            base = __shfl_sync(0xFFFFFFFFu, base, leader_lane);
            if (cum > 0) {
                unsigned long long* dst = candp + (size_t)gn * CAND_CAP;
#pragma unroll
                for (int i = 0; i < 8; ++i) {
                    if (pb[i] & (1u << lane)) {
                        int pos = base + rank[i];
                        if (pos < CAND_CAP) {
                            int gm = m0 + row_off + i;
                            dst[pos] = ((unsigned long long)float_key(acc[i][j]) << 32)
                                       | (unsigned int)gm;
                        }
                    }
                }
            }
        }
    }
}

// ----------------------------- threshold from subset -------------------------
// Also zeroes the per-row candidate counter (replaces zero_cnt kernel).
__global__ __launch_bounds__(256)
void thr_kernel(const float* __restrict__ sd, float* __restrict__ thr,
                int* __restrict__ cnt) {
    int warp = (blockIdx.x * blockDim.x + threadIdx.x) >> 5;
    int lane = threadIdx.x & 31;
    if (warp >= NROWS) return;
    const float4* row4 = (const float4*)(sd + (size_t)warp * NSUB);

    const unsigned long long SENT = 0xFFFFFFFFFFFFFFFFULL;
    unsigned long long loc[KNN];
#pragma unroll
    for (int t = 0; t < KNN; ++t) loc[t] = SENT;

#pragma unroll
    for (int g = 0; g < 2; ++g) {
        float4 v = row4[g * 32 + lane];
        unsigned int j = (g * 32 + lane) * 4;
        chain_insert20(loc, ((unsigned long long)float_key(v.x) << 32) | (j + 0));
        chain_insert20(loc, ((unsigned long long)float_key(v.y) << 32) | (j + 1));
        chain_insert20(loc, ((unsigned long long)float_key(v.z) << 32) | (j + 2));
        chain_insert20(loc, ((unsigned long long)float_key(v.w) << 32) | (j + 3));
    }

    float thr_f = 0.f;
#pragma unroll
    for (int s = 0; s < KNN; ++s) {
        unsigned long long v = loc[0];
        int wl = lane;
#pragma unroll
        for (int off = 16; off > 0; off >>= 1) {
            unsigned long long ov = __shfl_down_sync(0xFFFFFFFFu, v, off);
            int owl = __shfl_down_sync(0xFFFFFFFFu, wl, off);
            if (ov < v) { v = ov; wl = owl; }
        }
        unsigned long long win = __shfl_sync(0xFFFFFFFFu, v, 0);
        int wlane = __shfl_sync(0xFFFFFFFFu, wl, 0);
        if (lane == wlane) {
#pragma unroll
            for (int t = 0; t < KNN - 1; ++t) loc[t] = loc[t + 1];
            loc[KNN - 1] = SENT;
        }
        thr_f = key_to_float((unsigned int)(win >> 32));
    }
    if (lane == 0) {
        thr[warp] = thr_f;
        cnt[warp * CNT_STRIDE] = 0;
    }
}

// ----------------------------- exact top-20 from candidates ------------------
__global__ __launch_bounds__(256)
void cand_topk_kernel(const unsigned long long* __restrict__ cand,
                      const int* __restrict__ cnt, int* __restrict__ out) {
    int warp = (blockIdx.x * blockDim.x + threadIdx.x) >> 5;
    int lane = threadIdx.x & 31;
    if (warp >= NROWS) return;
    int c = cnt[warp * CNT_STRIDE];
    if (c > CAND_CAP) c = CAND_CAP;
    const unsigned long long* buf = cand + (size_t)warp * CAND_CAP;

    const unsigned long long SENT = 0xFFFFFFFFFFFFFFFFULL;
    unsigned long long loc[KNN];
#pragma unroll
    for (int t = 0; t < KNN; ++t) loc[t] = SENT;
    for (int i = lane; i < c; i += 32) chain_insert20(loc, buf[i]);

#pragma unroll
    for (int s = 0; s < KNN; ++s) {
        unsigned long long v = loc[0];
        int wl = lane;
#pragma unroll
        for (int off = 16; off > 0; off >>= 1) {
            unsigned long long ov = __shfl_down_sync(0xFFFFFFFFu, v, off);
            int owl = __shfl_down_sync(0xFFFFFFFFu, wl, off);
            if (ov < v) { v = ov; wl = owl; }
        }
        unsigned long long win = __shfl_sync(0xFFFFFFFFu, v, 0);
        int wlane = __shfl_sync(0xFFFFFFFFu, wl, 0);
        if (lane == 0) out[(size_t)warp * KNN + s] = (int)(win & 0xFFFFFFFFu);
        if (lane == wlane) {
#pragma unroll
            for (int t = 0; t < KNN - 1; ++t) loc[t] = loc[t + 1];
            loc[KNN - 1] = SENT;
        }
    }
}

// ----------------------------- gather + epilogue (+ fused sqnorm) ------------
__global__ void gather_max_bn_kernel(const float* __restrict__ PQ,
                                     const int* __restrict__ idx,
                                     const float* __restrict__ gamma,
                                     const float* __restrict__ beta,
                                     float* __restrict__ out, int outLd, int C,
                                     float* __restrict__ sqout) {
    __shared__ int sidx[KNN];
    __shared__ float red[8];
    int point = blockIdx.x;
    int b = point / NPTS;
    if (threadIdx.x < KNN) sidx[threadIdx.x] = idx[(size_t)point * KNN + threadIdx.x];
    __syncthreads();
    int c = threadIdx.x;
    int ld = 2 * C;
    float m = -FLT_MAX;
#pragma unroll 4
    for (int j = 0; j < KNN; ++j) {
        size_t row = (size_t)b * NPTS + sidx[j];
        m = fmaxf(m, PQ[row * ld + c]);
    }
    float v = m + PQ[(size_t)point * ld + C + c];
    float s = gamma[c] * rsqrtf(1.0f + EPS_BN);
    v = v * s + beta[c];
    v = (v >= 0.f) ? v : SLOPE * v;
    out[(size_t)point * outLd + c] = v;

    // fused sqnorm of the slice just written (next layer's input)
    float ss = v * v;
#pragma unroll
    for (int off = 16; off > 0; off >>= 1)
        ss += __shfl_down_sync(0xFFFFFFFFu, ss, off);
    int wid = c >> 5;
    if ((c & 31) == 0) red[wid] = ss;
    __syncthreads();
    if (c == 0) {
        float tot = 0.f;
        int nwarps = C >> 5;
        for (int w = 0; w < nwarps; ++w) tot += red[w];
        sqout[point] = tot;
    }
}

// ----------------------------- two-stage pool --------------------------------
#define PCHUNK 32
#define PSTEP (NPTS / PCHUNK)

__global__ void reduce1_kernel(const float* __restrict__ y,
                               float* __restrict__ pmax, float* __restrict__ psum) {
    int b = blockIdx.y;
    int q = blockIdx.x;
    int c = threadIdx.x;
    const float* p = y + ((size_t)b * NPTS + (size_t)q * PSTEP) * 512 + c;
    float mx = -FLT_MAX, sm = 0.f;
#pragma unroll 4
    for (int n = 0; n < PSTEP; ++n) {
        float v = p[(size_t)n * 512];
        mx = fmaxf(mx, v);
        sm += v;
    }
    pmax[(b * PCHUNK + q) * 512 + c] = mx;
    psum[(b * PCHUNK + q) * 512 + c] = sm;
}

__global__ void reduce2_kernel(const float* __restrict__ pmax,
                               const float* __restrict__ psum,
                               float* __restrict__ out) {
    int b = blockIdx.x;
    int c = threadIdx.x;
    float mx = -FLT_MAX, sm = 0.f;
#pragma unroll
    for (int q = 0; q < PCHUNK; ++q) {
        mx = fmaxf(mx, pmax[(b * PCHUNK + q) * 512 + c]);
        sm += psum[(b * PCHUNK + q) * 512 + c];
    }
    out[b * 1024 + c]       = mx;
    out[b * 1024 + 512 + c] = sm * (1.0f / NPTS);
}

// ----------------------------- host driver ----------------------------------

static void run_edge_conv(const float* X, int lda, int D, int C,
                          const float* W, const float* g, const float* b,
                          float* h_out_col,
                          float* p_sq, float* p_sub, float* p_thr, int* p_cnt,
                          unsigned long long* p_cand, int* p_idx,
                          float* p_PQ, float* p_wc) {
    // NOTE: p_sq for this layer must already be populated (sqnorm for layer 1,
    // fused into gather for layers 2-4).

    // subset dist: every point vs first NSUB points of its batch
    dim3 gs(NSUB / TBN, NPTS / TBM, BATCH);
    gemm_nt_kernel<1><<<gs, 256>>>(X, lda, (long long)NPTS * lda,
                                   X, lda, (long long)NPTS * lda,
                                   p_sub, NSUB, (long long)NPTS * NSUB,
                                   NPTS, NSUB, D,
                                   p_sq, NPTS, nullptr, nullptr);

    thr_kernel<<<NROWS / 8, 256>>>(p_sub, p_thr, p_cnt);

    // symmetric triangular filter (no dist store)
    dim3 gd(NPAIRS, 1, BATCH);
    dist_filter_kernel<<<gd, 256>>>(X, lda, D, p_sq, p_thr, p_cnt, p_cand);

    cand_topk_kernel<<<NROWS / 8, 256>>>(p_cand, p_cnt, p_idx);

    wcomb_kernel<<<(2 * C * D + 255) / 256, 256>>>(W, p_wc, C, D);

    dim3 gp((2 * C) / TBN, NROWS / TBM, 1);
    gemm_nt_kernel<0><<<gp, 256>>>(X, lda, 0, p_wc, D, 0,
                                   p_PQ, 2 * C, 0, NROWS, 2 * C, D,
                                   nullptr, 0, nullptr, nullptr);

    // gather + bn/lrelu + fused sqnorm for the next layer
    gather_max_bn_kernel<<<NROWS, C>>>(p_PQ, p_idx, g, b, h_out_col, 512, C, p_sq);
}

extern "C" void kernel_launch(void* const* d_in, const int* in_sizes, int n_in,
                              void* d_out, int out_size) {
    const float* x = (const float*)d_in[0];
    int wb = 1;
    if (n_in > 1 && in_sizes[1] == 1) wb = 2;

    const float* W1 = (const float*)d_in[wb + 0];
    const float* g1 = (const float*)d_in[wb + 1];
    const float* b1 = (const float*)d_in[wb + 2];
    const float* W2 = (const float*)d_in[wb + 3];
    const float* g2 = (const float*)d_in[wb + 4];
    const float* b2 = (const float*)d_in[wb + 5];
    const float* W3 = (const float*)d_in[wb + 6];
    const float* g3 = (const float*)d_in[wb + 7];
    const float* b3 = (const float*)d_in[wb + 8];
    const float* W4 = (const float*)d_in[wb + 9];
    const float* g4 = (const float*)d_in[wb + 10];
    const float* b4 = (const float*)d_in[wb + 11];
    const float* W5 = (const float*)d_in[wb + 12];
    const float* g5 = (const float*)d_in[wb + 13];
    const float* b5 = (const float*)d_in[wb + 14];

    void *p;
    cudaGetSymbolAddress(&p, g_x0);    float* x0   = (float*)p;
    cudaGetSymbolAddress(&p, g_h);     float* h    = (float*)p;
    cudaGetSymbolAddress(&p, g_sq);    float* sq   = (float*)p;
    cudaGetSymbolAddress(&p, g_idx);   int*   idx  = (int*)p;
    cudaGetSymbolAddress(&p, g_PQ);    float* PQ   = (float*)p;
    cudaGetSymbolAddress(&p, g_wcomb); float* wc   = (float*)p;
    cudaGetSymbolAddress(&p, g_y);     float* y    = (float*)p;
    cudaGetSymbolAddress(&p, g_thr);   float* thr  = (float*)p;
    cudaGetSymbolAddress(&p, g_cnt);   int*   cnt  = (int*)p;
    cudaGetSymbolAddress(&p, g_cand);  unsigned long long* cand = (unsigned long long*)p;
    cudaGetSymbolAddress(&p, g_pmax);  float* pmax = (float*)p;
    cudaGetSymbolAddress(&p, g_psum);  float* psum = (float*)p;

    transpose_x_kernel<<<(BATCH * 3 * NPTS + 255) / 256, 256>>>(x, x0);
    sqnorm_kernel<<<(NROWS + 255) / 256, 256>>>(x0, 3, 3, sq);

    run_edge_conv(x0,      3,   3,   64,  W1, g1, b1, h + 0,   sq, y, thr, cnt, cand, idx, PQ, wc);
    run_edge_conv(h + 0,   512, 64,  64,  W2, g2, b2, h + 64,  sq, y, thr, cnt, cand, idx, PQ, wc);
    run_edge_conv(h + 64,  512, 64,  128, W3, g3, b3, h + 128, sq, y, thr, cnt, cand, idx, PQ, wc);
    run_edge_conv(h + 128, 512, 128, 256, W4, g4, b4, h + 256, sq, y, thr, cnt, cand, idx, PQ, wc);

    dim3 gf(512 / TBN, NROWS / TBM, 1);
    gemm_nt_kernel<2><<<gf, 256>>>(h, 512, 0, W5, 512, 0,
                                   y, 512, 0, NROWS, 512, 512,
                                   nullptr, 0, g5, b5);

    reduce1_kernel<<<dim3(PCHUNK, BATCH), 512>>>(y, pmax, psum);
    reduce2_kernel<<<BATCH, 512>>>(pmax, psum, (float*)d_out);
}

// round 9
// speedup vs baseline: 1.9189x; 1.0697x over previous
#include <cuda_runtime.h>
#include <cuda_bf16.h>
#include <float.h>

// ---------------------------------------------------------------------------
// DGCNN forward, restructured:
//   EdgeConv(X, W, g, b):  P = X W_a^T ; Q = X (W_b - W_a)^T
//   out[n,c] = bn_lrelu( max_j P[knn(n,j), c] + Q[n,c] )
// kNN via threshold-first filtering (dist matrix never materialized).
// GEMM inner loops use packed fp32 FMA (fma.rn.f32x2) — bitwise-identical to
// scalar FFMA per lane, 2x math issue rate.
// ---------------------------------------------------------------------------

#define BATCH 8
#define NPTS  4096
#define KNN   20
#define NROWS (BATCH * NPTS)   // 32768
#define EPS_BN 1e-5f
#define SLOPE 0.2f
#define NSUB  256
#define CAND_CAP 2048
#define CNT_STRIDE 8           // 32B padding between counters
#define NT 32                  // 4096/128 tiles per side
#define NPAIRS (NT * (NT + 1) / 2)   // 528

// ----------------------------- scratch (device globals) --------------------
__device__ float g_x0[NROWS * 3];
__device__ float g_h[(size_t)NROWS * 512];
__device__ float g_sq[NROWS];
__device__ int   g_idx[NROWS * KNN];
__device__ float g_PQ[(size_t)NROWS * 512];
__device__ float g_wcomb[512 * 128];
__device__ float g_y[(size_t)NROWS * 512];        // final acts; also subset-dist scratch
__device__ float g_thr[NROWS];
__device__ int   g_cnt[NROWS * CNT_STRIDE];
__device__ unsigned long long g_cand[(size_t)NROWS * CAND_CAP];
__device__ float g_pmax[BATCH * 32 * 512];
__device__ float g_psum[BATCH * 32 * 512];

// ----------------------------- helpers ---------------------------------------

__device__ __forceinline__ unsigned int float_key(float f) {
    unsigned int b = __float_as_uint(f);
    unsigned int mask = (unsigned int)(((int)b) >> 31) | 0x80000000u;
    return b ^ mask;   // monotone: smaller float -> smaller uint
}
// Identical FP sequence in subset GEMM and filter kernel (no reassociation).
__device__ __forceinline__ float dist_val(float sm, float sn, float acc) {
    return __fmaf_rn(-2.0f, acc, __fadd_rn(sm, sn));
}
__device__ __forceinline__ void chain_insert20(unsigned long long loc[KNN],
                                               unsigned long long v) {
#pragma unroll
    for (int t = 0; t < KNN; ++t) {
        if (v < loc[t]) { unsigned long long tmp = loc[t]; loc[t] = v; v = tmp; }
    }
}

// packed f32x2 ops (Blackwell): each lane is an exact rn fp32 FMA
__device__ __forceinline__ unsigned long long pack2(float lo, float hi) {
    unsigned long long d;
    asm("mov.b64 %0, {%1, %2};" : "=l"(d) : "r"(__float_as_uint(lo)), "r"(__float_as_uint(hi)));
    return d;
}
__device__ __forceinline__ void unpack2(unsigned long long v, float& lo, float& hi) {
    unsigned int a, b;
    asm("mov.b64 {%0, %1}, %2;" : "=r"(a), "=r"(b) : "l"(v));
    lo = __uint_as_float(a);
    hi = __uint_as_float(b);
}
__device__ __forceinline__ unsigned long long fma2(unsigned long long a,
                                                   unsigned long long b,
                                                   unsigned long long c) {
    unsigned long long d;
    asm("fma.rn.f32x2 %0, %1, %2, %3;" : "=l"(d) : "l"(a), "l"(b), "l"(c));
    return d;
}

// ----------------------------- small kernels --------------------------------

__global__ void transpose_x_kernel(const float* __restrict__ x, float* __restrict__ xt) {
    int i = blockIdx.x * blockDim.x + threadIdx.x;
    const int total = BATCH * 3 * NPTS;
    if (i >= total) return;
    int b = i / (3 * NPTS);
    int rem = i % (3 * NPTS);
    int d = rem / NPTS;
    int n = rem % NPTS;
    xt[((size_t)b * NPTS + n) * 3 + d] = x[i];
}

__global__ void sqnorm_kernel(const float* __restrict__ X, int lda, int D,
                              float* __restrict__ sq) {
    int i = blockIdx.x * blockDim.x + threadIdx.x;
    if (i >= NROWS) return;
    const float* r = X + (size_t)i * lda;
    float s = 0.f;
    for (int d = 0; d < D; ++d) s += r[d] * r[d];
    sq[i] = s;
}

// Wc rows 0..C-1 = W_a ; rows C..2C-1 = W_b - W_a
__global__ void wcomb_kernel(const float* __restrict__ W, float* __restrict__ Wc,
                             int C, int D) {
    int i = blockIdx.x * blockDim.x + threadIdx.x;
    if (i >= 2 * C * D) return;
    int c = i / D, d = i % D;
    Wc[i] = (c < C) ? W[c * 2 * D + d]
                    : (W[(c - C) * 2 * D + D + d] - W[(c - C) * 2 * D + d]);
}

// ----------------------------- GEMM (store modes) ----------------------------
// NT GEMM:  C[m,n] = sum_k A[m,k] * B[n,k]
// MODE 0: plain store ; MODE 1: dist store ; MODE 2: bn+lrelu store
#define TBM 128
#define TBN 128
#define TBK 8

template <int MODE>
__global__ __launch_bounds__(256, 2)
void gemm_nt_kernel(const float* __restrict__ A, int lda, long long sA,
                    const float* __restrict__ Bw, int ldb, long long sB,
                    float* __restrict__ C, int ldc, long long sC,
                    int M, int Nn, int K,
                    const float* __restrict__ sq, long long sSq,
                    const float* __restrict__ gamma, const float* __restrict__ beta) {
    int bz = blockIdx.z;
    A  += (long long)bz * sA;
    Bw += (long long)bz * sB;
    C  += (long long)bz * sC;
    const float* sqp = (MODE == 1) ? (sq + (long long)bz * sSq) : nullptr;

    __shared__ float As[2][TBK][TBM + 4];
    __shared__ float Bs[2][TBK][TBN + 4];

    const int m0 = blockIdx.y * TBM;
    const int n0 = blockIdx.x * TBN;
    const int tid = threadIdx.x;
    const int tn = tid % 16;
    const int tm = tid / 16;

    float acc[8][8];

    const bool vec = ((lda % 4) == 0) && ((ldb % 4) == 0) && ((K % TBK) == 0);
    const int lr = tid >> 1;
    const int lp = (tid & 1) * 4;

    if (vec) {
        unsigned long long acc2[8][4];
#pragma unroll
        for (int i = 0; i < 8; ++i)
#pragma unroll
            for (int jj = 0; jj < 4; ++jj) acc2[i][jj] = 0ULL;
        {
            float4 va = *(const float4*)(A + (long long)(m0 + lr) * lda + lp);
            float4 vb = *(const float4*)(Bw + (long long)(n0 + lr) * ldb + lp);
            As[0][lp + 0][lr] = va.x; As[0][lp + 1][lr] = va.y;
            As[0][lp + 2][lr] = va.z; As[0][lp + 3][lr] = va.w;
            Bs[0][lp + 0][lr] = vb.x; Bs[0][lp + 1][lr] = vb.y;
            Bs[0][lp + 2][lr] = vb.z; Bs[0][lp + 3][lr] = vb.w;
        }
        __syncthreads();
        int cur = 0;
        for (int k0 = 0; k0 < K; k0 += TBK) {
            const bool has_next = (k0 + TBK) < K;
            float4 na, nb;
            if (has_next) {
                na = *(const float4*)(A + (long long)(m0 + lr) * lda + k0 + TBK + lp);
                nb = *(const float4*)(Bw + (long long)(n0 + lr) * ldb + k0 + TBK + lp);
            }
#pragma unroll
            for (int kk = 0; kk < TBK; ++kk) {
                const float4* pa = (const float4*)&As[cur][kk][tm * 8];
                const float4* pb = (const float4*)&Bs[cur][kk][tn * 8];
                float4 a0 = pa[0], a1 = pa[1];
                float4 b0 = pb[0], b1 = pb[1];
                unsigned long long rb2[4];
                rb2[0] = pack2(b0.x, b0.y); rb2[1] = pack2(b0.z, b0.w);
                rb2[2] = pack2(b1.x, b1.y); rb2[3] = pack2(b1.z, b1.w);
                float ra[8];
                ra[0] = a0.x; ra[1] = a0.y; ra[2] = a0.z; ra[3] = a0.w;
                ra[4] = a1.x; ra[5] = a1.y; ra[6] = a1.z; ra[7] = a1.w;
#pragma unroll
                for (int i = 0; i < 8; ++i) {
                    unsigned long long ra2 = pack2(ra[i], ra[i]);
#pragma unroll
                    for (int jj = 0; jj < 4; ++jj)
                        acc2[i][jj] = fma2(ra2, rb2[jj], acc2[i][jj]);
                }
            }
            if (has_next) {
                int nxt = cur ^ 1;
                As[nxt][lp + 0][lr] = na.x; As[nxt][lp + 1][lr] = na.y;
                As[nxt][lp + 2][lr] = na.z; As[nxt][lp + 3][lr] = na.w;
                Bs[nxt][lp + 0][lr] = nb.x; Bs[nxt][lp + 1][lr] = nb.y;
                Bs[nxt][lp + 2][lr] = nb.z; Bs[nxt][lp + 3][lr] = nb.w;
            }
            __syncthreads();
            cur ^= 1;
        }
#pragma unroll
        for (int i = 0; i < 8; ++i)
#pragma unroll
            for (int jj = 0; jj < 4; ++jj)
                unpack2(acc2[i][jj], acc[i][2 * jj], acc[i][2 * jj + 1]);
    } else {
#pragma unroll
        for (int i = 0; i < 8; ++i)
#pragma unroll
            for (int j = 0; j < 8; ++j) acc[i][j] = 0.f;
        for (int k0 = 0; k0 < K; k0 += TBK) {
            for (int i = tid; i < TBM * TBK; i += 256) {
                int mm = i % TBM, kk = i / TBM;
                int gk = k0 + kk;
                As[0][kk][mm] = (gk < K) ? A[(long long)(m0 + mm) * lda + gk] : 0.f;
            }
            for (int i = tid; i < TBN * TBK; i += 256) {
                int nn = i % TBN, kk = i / TBN;
                int gk = k0 + kk;
                Bs[0][kk][nn] = (gk < K) ? Bw[(long long)(n0 + nn) * ldb + gk] : 0.f;
            }
            __syncthreads();
#pragma unroll
            for (int kk = 0; kk < TBK; ++kk) {
                float ra[8], rb[8];
                const float4* pa = (const float4*)&As[0][kk][tm * 8];
                const float4* pb = (const float4*)&Bs[0][kk][tn * 8];
                float4 a0 = pa[0], a1 = pa[1];
                float4 b0 = pb[0], b1 = pb[1];
                ra[0] = a0.x; ra[1] = a0.y; ra[2] = a0.z; ra[3] = a0.w;
                ra[4] = a1.x; ra[5] = a1.y; ra[6] = a1.z; ra[7] = a1.w;
                rb[0] = b0.x; rb[1] = b0.y; rb[2] = b0.z; rb[3] = b0.w;
                rb[4] = b1.x; rb[5] = b1.y; rb[6] = b1.z; rb[7] = b1.w;
#pragma unroll
                for (int i = 0; i < 8; ++i)
#pragma unroll
                    for (int j = 0; j < 8; ++j) acc[i][j] += ra[i] * rb[j];
            }
            __syncthreads();
        }
    }

#pragma unroll
    for (int i = 0; i < 8; ++i) {
        int gm = m0 + tm * 8 + i;
        float* crow = C + (long long)gm * ldc + n0 + tn * 8;
        float v[8];
        if (MODE == 1) {
            float sm = sqp[gm];
#pragma unroll
            for (int j = 0; j < 8; ++j) {
                int gn = n0 + tn * 8 + j;
                v[j] = dist_val(sm, sqp[gn], acc[i][j]);
            }
        } else if (MODE == 2) {
#pragma unroll
            for (int j = 0; j < 8; ++j) {
                int gn = n0 + tn * 8 + j;
                float s = gamma[gn] * rsqrtf(1.0f + EPS_BN);
                float t = acc[i][j] * s + beta[gn];
                v[j] = (t >= 0.f) ? t : SLOPE * t;
            }
        } else {
#pragma unroll
            for (int j = 0; j < 8; ++j) v[j] = acc[i][j];
        }
        ((float4*)crow)[0] = make_float4(v[0], v[1], v[2], v[3]);
        ((float4*)crow)[1] = make_float4(v[4], v[5], v[6], v[7]);
    }
}

// ----------------------- symmetric dist filter (triangular) ------------------
// Upper block-triangle tiles only. Warp owns a 32x64 subtile (4x2 warp grid,
// lane = ly*8+lx, each thread 8x8). Row push: 8-lane groups (ly fixed).
// Col push (off-diagonal tiles only): 4-lane strided groups (lx fixed).
__global__ __launch_bounds__(256, 2)
void dist_filter_kernel(const float* __restrict__ X, int lda, int K,
                        const float* __restrict__ sq,
                        const float* __restrict__ thr,
                        int* __restrict__ cnt,
                        unsigned long long* __restrict__ cand) {
    const int bz = blockIdx.z;
    const float* A = X + (long long)bz * NPTS * lda;
    const float* sqp = sq + (long long)bz * NPTS;
    const float* thrp = thr + (long long)bz * NPTS;
    int* cntp = cnt + (long long)bz * NPTS * CNT_STRIDE;
    unsigned long long* candp = cand + (size_t)bz * NPTS * CAND_CAP;

    // triangular decode: pair index -> (ty, tx), tx >= ty
    int t = blockIdx.x, ty = 0;
    while (t >= NT - ty) { t -= NT - ty; ++ty; }
    const int tx = ty + t;
    const int m0 = ty * TBM;
    const int n0 = tx * TBN;
    const bool offdiag = (tx > ty);

    __shared__ float As[2][TBK][TBM + 4];
    __shared__ float Bs[2][TBK][TBN + 4];

    const int tid = threadIdx.x;
    const int lane = tid & 31;
    const int warp = tid >> 5;
    const int wy = warp >> 1;            // 0..3
    const int wx = warp & 1;             // 0..1
    const int ly = lane >> 3;            // 0..3
    const int lx = lane & 7;             // 0..7
    const int row_off = wy * 32 + ly * 8;
    const int col_off = wx * 64 + lx * 8;

    float acc[8][8];

    const bool vec = ((lda % 4) == 0) && ((K % TBK) == 0);
    const int lr = tid >> 1;
    const int lp = (tid & 1) * 4;

    if (vec) {
        unsigned long long acc2[8][4];
#pragma unroll
        for (int i = 0; i < 8; ++i)
#pragma unroll
            for (int jj = 0; jj < 4; ++jj) acc2[i][jj] = 0ULL;
        {
            float4 va = *(const float4*)(A + (long long)(m0 + lr) * lda + lp);
            float4 vb = *(const float4*)(A + (long long)(n0 + lr) * lda + lp);
            As[0][lp + 0][lr] = va.x; As[0][lp + 1][lr] = va.y;
            As[0][lp + 2][lr] = va.z; As[0][lp + 3][lr] = va.w;
            Bs[0][lp + 0][lr] = vb.x; Bs[0][lp + 1][lr] = vb.y;
            Bs[0][lp + 2][lr] = vb.z; Bs[0][lp + 3][lr] = vb.w;
        }
        __syncthreads();
        int cur = 0;
        for (int k0 = 0; k0 < K; k0 += TBK) {
            const bool has_next = (k0 + TBK) < K;
            float4 na, nb;
            if (has_next) {
                na = *(const float4*)(A + (long long)(m0 + lr) * lda + k0 + TBK + lp);
                nb = *(const float4*)(A + (long long)(n0 + lr) * lda + k0 + TBK + lp);
            }
#pragma unroll
            for (int kk = 0; kk < TBK; ++kk) {
                const float4* pa = (const float4*)&As[cur][kk][row_off];
                const float4* pb = (const float4*)&Bs[cur][kk][col_off];
                float4 a0 = pa[0], a1 = pa[1];
                float4 b0 = pb[0], b1 = pb[1];
                unsigned long long rb2[4];
                rb2[0] = pack2(b0.x, b0.y); rb2[1] = pack2(b0.z, b0.w);
                rb2[2] = pack2(b1.x, b1.y); rb2[3] = pack2(b1.z, b1.w);
                float ra[8];
                ra[0] = a0.x; ra[1] = a0.y; ra[2] = a0.z; ra[3] = a0.w;
                ra[4] = a1.x; ra[5] = a1.y; ra[6] = a1.z; ra[7] = a1.w;
#pragma unroll
                for (int i = 0; i < 8; ++i) {
                    unsigned long long ra2 = pack2(ra[i], ra[i]);
#pragma unroll
                    for (int jj = 0; jj < 4; ++jj)
                        acc2[i][jj] = fma2(ra2, rb2[jj], acc2[i][jj]);
                }
            }
            if (has_next) {
                int nxt = cur ^ 1;
                As[nxt][lp + 0][lr] = na.x; As[nxt][lp + 1][lr] = na.y;
                As[nxt][lp + 2][lr] = na.z; As[nxt][lp + 3][lr] = na.w;
                Bs[nxt][lp + 0][lr] = nb.x; Bs[nxt][lp + 1][lr] = nb.y;
                Bs[nxt][lp + 2][lr] = nb.z; Bs[nxt][lp + 3][lr] = nb.w;
            }
            __syncthreads();
            cur ^= 1;
        }
#pragma unroll
        for (int i = 0; i < 8; ++i)
#pragma unroll
            for (int jj = 0; jj < 4; ++jj)
                unpack2(acc2[i][jj], acc[i][2 * jj], acc[i][2 * jj + 1]);
    } else {
#pragma unroll
        for (int i = 0; i < 8; ++i)
#pragma unroll
            for (int j = 0; j < 8; ++j) acc[i][j] = 0.f;
        for (int k0 = 0; k0 < K; k0 += TBK) {
            for (int i = tid; i < TBM * TBK; i += 256) {
                int mm = i % TBM, kk = i / TBM;
                int gk = k0 + kk;
                As[0][kk][mm] = (gk < K) ? A[(long long)(m0 + mm) * lda + gk] : 0.f;
            }
            for (int i = tid; i < TBN * TBK; i += 256) {
                int nn = i % TBN, kk = i / TBN;
                int gk = k0 + kk;
                Bs[0][kk][nn] = (gk < K) ? A[(long long)(n0 + nn) * lda + gk] : 0.f;
            }
            __syncthreads();
#pragma unroll
            for (int kk = 0; kk < TBK; ++kk) {
                float ra[8], rb[8];
                const float4* pa = (const float4*)&As[0][kk][row_off];
                const float4* pb = (const float4*)&Bs[0][kk][col_off];
                float4 a0 = pa[0], a1 = pa[1];
                float4 b0 = pb[0], b1 = pb[1];
                ra[0] = a0.x; ra[1] = a0.y; ra[2] = a0.z; ra[3] = a0.w;
                ra[4] = a1.x; ra[5] = a1.y; ra[6] = a1.z; ra[7] = a1.w;
                rb[0] = b0.x; rb[1] = b0.y; rb[2] = b0.z; rb[3] = b0.w;
                rb[4] = b1.x; rb[5] = b1.y; rb[6] = b1.z; rb[7] = b1.w;
#pragma unroll
                for (int i = 0; i < 8; ++i)
#pragma unroll
                    for (int j = 0; j < 8; ++j) acc[i][j] += ra[i] * rb[j];
            }
            __syncthreads();
        }
    }

    // v[i][j] in-place
    float sm[8], sn[8], trr[8], trc[8];
#pragma unroll
    for (int i = 0; i < 8; ++i) {
        sm[i] = sqp[m0 + row_off + i];
        trr[i] = thrp[m0 + row_off + i];
    }
#pragma unroll
    for (int j = 0; j < 8; ++j) {
        sn[j] = sqp[n0 + col_off + j];
        trc[j] = thrp[n0 + col_off + j];
    }
#pragma unroll
    for (int i = 0; i < 8; ++i)
#pragma unroll
        for (int j = 0; j < 8; ++j)
            acc[i][j] = dist_val(sm[i], sn[j], acc[i][j]);

    // ---- row push: 8-lane groups (ly fixed), leader lane = ly*8 ----
    {
        const unsigned grp = 0xFFu << (ly * 8);
        const unsigned below = ((1u << lx) - 1u) << (ly * 8);
        const int leader_lane = ly * 8;
#pragma unroll
        for (int i = 0; i < 8; ++i) {
            const int gm = m0 + row_off + i;
            unsigned pb[8];
            int rank[8];
            int cum = 0;
#pragma unroll
            for (int j = 0; j < 8; ++j) {
                unsigned ball = __ballot_sync(0xFFFFFFFFu, acc[i][j] <= trr[i]) & grp;
                rank[j] = cum + __popc(ball & below);
                cum += __popc(ball);
                pb[j] = ball;
            }
            int base = 0;
            if (lx == 0 && cum > 0) base = atomicAdd(&cntp[gm * CNT_STRIDE], cum);
            base = __shfl_sync(0xFFFFFFFFu, base, leader_lane);
            if (cum > 0) {
                unsigned long long* dst = candp + (size_t)gm * CAND_CAP;
#pragma unroll
                for (int j = 0; j < 8; ++j) {
                    if (pb[j] & (1u << lane)) {
                        int pos = base + rank[j];
                        if (pos < CAND_CAP) {
                            int gn = n0 + col_off + j;
                            dst[pos] = ((unsigned long long)float_key(acc[i][j]) << 32)
                                       | (unsigned int)gn;
                        }
                    }
                }
            }
        }
    }

    // ---- col push (off-diagonal only): 4-lane strided groups (lx fixed) ----
    if (offdiag) {
        const unsigned grp = 0x01010101u << lx;
        const unsigned below = grp & ((1u << lane) - 1u);
        const int leader_lane = lx;        // ly==0 member
#pragma unroll
        for (int j = 0; j < 8; ++j) {
            const int gn = n0 + col_off + j;
            unsigned pb[8];
            int rank[8];
            int cum = 0;
#pragma unroll
            for (int i = 0; i < 8; ++i) {
                unsigned ball = __ballot_sync(0xFFFFFFFFu, acc[i][j] <= trc[j]) & grp;
                rank[i] = cum + __popc(ball & below);
                cum += __popc(ball);
                pb[i] = ball;
            }
            int base = 0;
            if (ly == 0 && cum > 0) base = atomicAdd(&cntp[gn * CNT_STRIDE], cum);
            base = __shfl_sync(0xFFFFFFFFu, base, leader_lane);
            if (cum > 0) {
                unsigned long long* dst = candp + (size_t)gn * CAND_CAP;
#pragma unroll
                for (int i = 0; i < 8; ++i) {
                    if (pb[i] & (1u << lane)) {
                        int pos = base + rank[i];
                        if (pos < CAND_CAP) {
                            int gm = m0 + row_off + i;
                            dst[pos] = ((unsigned long long)float_key(acc[i][j]) << 32)
                                       | (unsigned int)gm;
                        }
                    }
                }
            }
        }
    }
}

// ----------------------------- threshold from subset -------------------------
// Float-only selection (threshold needs the 20th VALUE, not indices); the 20th
// value equals the u64-key version's value part, so candidate sets are unchanged.
// Also zeroes the per-row candidate counter.
__global__ __launch_bounds__(256)
void thr_kernel(const float* __restrict__ sd, float* __restrict__ thr,
                int* __restrict__ cnt) {
    int warp = (blockIdx.x * blockDim.x + threadIdx.x) >> 5;
    int lane = threadIdx.x & 31;
    if (warp >= NROWS) return;
    const float4* row4 = (const float4*)(sd + (size_t)warp * NSUB);

    float loc[KNN];
#pragma unroll
    for (int t = 0; t < KNN; ++t) loc[t] = FLT_MAX;

#pragma unroll
    for (int g = 0; g < 2; ++g) {
        float4 v4 = row4[g * 32 + lane];
        float vals[4] = {v4.x, v4.y, v4.z, v4.w};
#pragma unroll
        for (int s = 0; s < 4; ++s) {
            float v = vals[s];
#pragma unroll
            for (int t = 0; t < KNN; ++t) {
                float mn = fminf(loc[t], v);
                v = fmaxf(loc[t], v);
                loc[t] = mn;
            }
        }
    }

    float thr_f = 0.f;
#pragma unroll
    for (int s = 0; s < KNN; ++s) {
        float v = loc[0];
#pragma unroll
        for (int off = 16; off > 0; off >>= 1)
            v = fminf(v, __shfl_xor_sync(0xFFFFFFFFu, v, off));
        unsigned m = __ballot_sync(0xFFFFFFFFu, loc[0] == v);
        int wlane = __ffs(m) - 1;
        if (lane == wlane) {
#pragma unroll
            for (int t = 0; t < KNN - 1; ++t) loc[t] = loc[t + 1];
            loc[KNN - 1] = FLT_MAX;
        }
        thr_f = v;
    }
    if (lane == 0) {
        thr[warp] = thr_f;
        cnt[warp * CNT_STRIDE] = 0;
    }
}

// ----------------------------- exact top-20 from candidates ------------------
__global__ __launch_bounds__(256)
void cand_topk_kernel(const unsigned long long* __restrict__ cand,
                      const int* __restrict__ cnt, int* __restrict__ out) {
    int warp = (blockIdx.x * blockDim.x + threadIdx.x) >> 5;
    int lane = threadIdx.x & 31;
    if (warp >= NROWS) return;
    int c = cnt[warp * CNT_STRIDE];
    if (c > CAND_CAP) c = CAND_CAP;
    const unsigned long long* buf = cand + (size_t)warp * CAND_CAP;

    const unsigned long long SENT = 0xFFFFFFFFFFFFFFFFULL;
    unsigned long long loc[KNN];
#pragma unroll
    for (int t = 0; t < KNN; ++t) loc[t] = SENT;
    for (int i = lane; i < c; i += 32) chain_insert20(loc, buf[i]);

#pragma unroll
    for (int s = 0; s < KNN; ++s) {
        unsigned long long v = loc[0];
        int wl = lane;
#pragma unroll
        for (int off = 16; off > 0; off >>= 1) {
            unsigned long long ov = __shfl_down_sync(0xFFFFFFFFu, v, off);
            int owl = __shfl_down_sync(0xFFFFFFFFu, wl, off);
            if (ov < v) { v = ov; wl = owl; }
        }
        unsigned long long win = __shfl_sync(0xFFFFFFFFu, v, 0);
        int wlane = __shfl_sync(0xFFFFFFFFu, wl, 0);
        if (lane == 0) out[(size_t)warp * KNN + s] = (int)(win & 0xFFFFFFFFu);
        if (lane == wlane) {
#pragma unroll
            for (int t = 0; t < KNN - 1; ++t) loc[t] = loc[t + 1];
            loc[KNN - 1] = SENT;
        }
    }
}

// ----------------------------- gather + epilogue (+ fused sqnorm) ------------
__global__ void gather_max_bn_kernel(const float* __restrict__ PQ,
                                     const int* __restrict__ idx,
                                     const float* __restrict__ gamma,
                                     const float* __restrict__ beta,
                                     float* __restrict__ out, int outLd, int C,
                                     float* __restrict__ sqout) {
    __shared__ int sidx[KNN];
    __shared__ float red[8];
    int point = blockIdx.x;
    int b = point / NPTS;
    if (threadIdx.x < KNN) sidx[threadIdx.x] = idx[(size_t)point * KNN + threadIdx.x];
    __syncthreads();
    int c = threadIdx.x;
    int ld = 2 * C;
    float m = -FLT_MAX;
#pragma unroll 4
    for (int j = 0; j < KNN; ++j) {
        size_t row = (size_t)b * NPTS + sidx[j];
        m = fmaxf(m, PQ[row * ld + c]);
    }
    float v = m + PQ[(size_t)point * ld + C + c];
    float s = gamma[c] * rsqrtf(1.0f + EPS_BN);
    v = v * s + beta[c];
    v = (v >= 0.f) ? v : SLOPE * v;
    out[(size_t)point * outLd + c] = v;

    // fused sqnorm of the slice just written (next layer's input)
    float ss = v * v;
#pragma unroll
    for (int off = 16; off > 0; off >>= 1)
        ss += __shfl_down_sync(0xFFFFFFFFu, ss, off);
    int wid = c >> 5;
    if ((c & 31) == 0) red[wid] = ss;
    __syncthreads();
    if (c == 0) {
        float tot = 0.f;
        int nwarps = C >> 5;
        for (int w = 0; w < nwarps; ++w) tot += red[w];
        sqout[point] = tot;
    }
}

// ----------------------------- two-stage pool --------------------------------
#define PCHUNK 32
#define PSTEP (NPTS / PCHUNK)

__global__ void reduce1_kernel(const float* __restrict__ y,
                               float* __restrict__ pmax, float* __restrict__ psum) {
    int b = blockIdx.y;
    int q = blockIdx.x;
    int c = threadIdx.x;
    const float* p = y + ((size_t)b * NPTS + (size_t)q * PSTEP) * 512 + c;
    float mx = -FLT_MAX, sm = 0.f;
#pragma unroll 4
    for (int n = 0; n < PSTEP; ++n) {
        float v = p[(size_t)n * 512];
        mx = fmaxf(mx, v);
        sm += v;
    }
    pmax[(b * PCHUNK + q) * 512 + c] = mx;
    psum[(b * PCHUNK + q) * 512 + c] = sm;
}

__global__ void reduce2_kernel(const float* __restrict__ pmax,
                               const float* __restrict__ psum,
                               float* __restrict__ out) {
    int b = blockIdx.x;
    int c = threadIdx.x;
    float mx = -FLT_MAX, sm = 0.f;
#pragma unroll
    for (int q = 0; q < PCHUNK; ++q) {
        mx = fmaxf(mx, pmax[(b * PCHUNK + q) * 512 + c]);
        sm += psum[(b * PCHUNK + q) * 512 + c];
    }
    out[b * 1024 + c]       = mx;
    out[b * 1024 + 512 + c] = sm * (1.0f / NPTS);
}

// ----------------------------- host driver ----------------------------------

static void run_edge_conv(const float* X, int lda, int D, int C,
                          const float* W, const float* g, const float* b,
                          float* h_out_col,
                          float* p_sq, float* p_sub, float* p_thr, int* p_cnt,
                          unsigned long long* p_cand, int* p_idx,
                          float* p_PQ, float* p_wc) {
    // subset dist: every point vs first NSUB points of its batch
    dim3 gs(NSUB / TBN, NPTS / TBM, BATCH);
    gemm_nt_kernel<1><<<gs, 256>>>(X, lda, (long long)NPTS * lda,
                                   X, lda, (long long)NPTS * lda,
                                   p_sub, NSUB, (long long)NPTS * NSUB,
                                   NPTS, NSUB, D,
                                   p_sq, NPTS, nullptr, nullptr);

    thr_kernel<<<NROWS / 8, 256>>>(p_sub, p_thr, p_cnt);

    // symmetric triangular filter (no dist store)
    dim3 gd(NPAIRS, 1, BATCH);
    dist_filter_kernel<<<gd, 256>>>(X, lda, D, p_sq, p_thr, p_cnt, p_cand);

    cand_topk_kernel<<<NROWS / 8, 256>>>(p_cand, p_cnt, p_idx);

    wcomb_kernel<<<(2 * C * D + 255) / 256, 256>>>(W, p_wc, C, D);

    dim3 gp((2 * C) / TBN, NROWS / TBM, 1);
    gemm_nt_kernel<0><<<gp, 256>>>(X, lda, 0, p_wc, D, 0,
                                   p_PQ, 2 * C, 0, NROWS, 2 * C, D,
                                   nullptr, 0, nullptr, nullptr);

    // gather + bn/lrelu + fused sqnorm for the next layer
    gather_max_bn_kernel<<<NROWS, C>>>(p_PQ, p_idx, g, b, h_out_col, 512, C, p_sq);
}

extern "C" void kernel_launch(void* const* d_in, const int* in_sizes, int n_in,
                              void* d_out, int out_size) {
    const float* x = (const float*)d_in[0];
    int wb = 1;
    if (n_in > 1 && in_sizes[1] == 1) wb = 2;

    const float* W1 = (const float*)d_in[wb + 0];
    const float* g1 = (const float*)d_in[wb + 1];
    const float* b1 = (const float*)d_in[wb + 2];
    const float* W2 = (const float*)d_in[wb + 3];
    const float* g2 = (const float*)d_in[wb + 4];
    const float* b2 = (const float*)d_in[wb + 5];
    const float* W3 = (const float*)d_in[wb + 6];
    const float* g3 = (const float*)d_in[wb + 7];
    const float* b3 = (const float*)d_in[wb + 8];
    const float* W4 = (const float*)d_in[wb + 9];
    const float* g4 = (const float*)d_in[wb + 10];
    const float* b4 = (const float*)d_in[wb + 11];
    const float* W5 = (const float*)d_in[wb + 12];
    const float* g5 = (const float*)d_in[wb + 13];
    const float* b5 = (const float*)d_in[wb + 14];

    void *p;
    cudaGetSymbolAddress(&p, g_x0);    float* x0   = (float*)p;
    cudaGetSymbolAddress(&p, g_h);     float* h    = (float*)p;
    cudaGetSymbolAddress(&p, g_sq);    float* sq   = (float*)p;
    cudaGetSymbolAddress(&p, g_idx);   int*   idx  = (int*)p;
    cudaGetSymbolAddress(&p, g_PQ);    float* PQ   = (float*)p;
    cudaGetSymbolAddress(&p, g_wcomb); float* wc   = (float*)p;
    cudaGetSymbolAddress(&p, g_y);     float* y    = (float*)p;
    cudaGetSymbolAddress(&p, g_thr);   float* thr  = (float*)p;
    cudaGetSymbolAddress(&p, g_cnt);   int*   cnt  = (int*)p;
    cudaGetSymbolAddress(&p, g_cand);  unsigned long long* cand = (unsigned long long*)p;
    cudaGetSymbolAddress(&p, g_pmax);  float* pmax = (float*)p;
    cudaGetSymbolAddress(&p, g_psum);  float* psum = (float*)p;

    transpose_x_kernel<<<(BATCH * 3 * NPTS + 255) / 256, 256>>>(x, x0);
    sqnorm_kernel<<<(NROWS + 255) / 256, 256>>>(x0, 3, 3, sq);

    run_edge_conv(x0,      3,   3,   64,  W1, g1, b1, h + 0,   sq, y, thr, cnt, cand, idx, PQ, wc);
    run_edge_conv(h + 0,   512, 64,  64,  W2, g2, b2, h + 64,  sq, y, thr, cnt, cand, idx, PQ, wc);
    run_edge_conv(h + 64,  512, 64,  128, W3, g3, b3, h + 128, sq, y, thr, cnt, cand, idx, PQ, wc);
    run_edge_conv(h + 128, 512, 128, 256, W4, g4, b4, h + 256, sq, y, thr, cnt, cand, idx, PQ, wc);

    dim3 gf(512 / TBN, NROWS / TBM, 1);
    gemm_nt_kernel<2><<<gf, 256>>>(h, 512, 0, W5, 512, 0,
                                   y, 512, 0, NROWS, 512, 512,
                                   nullptr, 0, g5, b5);

    reduce1_kernel<<<dim3(PCHUNK, BATCH), 512>>>(y, pmax, psum);
    reduce2_kernel<<<BATCH, 512>>>(pmax, psum, (float*)d_out);
}